// round 2
// baseline (speedup 1.0000x reference)
#include <cuda_runtime.h>
#include <math.h>

#define TEMP 0.0005f
#define B_   32
#define CMEL 80
#define CTXT 512
#define CATT 80
#define T1_  1600
#define T2_  400

// ---------------- scratch (device globals; no allocation) ----------------
__device__ float g_kb [B_ * CTXT];            // speaker bias for keys
__device__ float g_qb [B_ * CMEL];            // speaker bias for queries
__device__ float g_k1 [B_ * 1024 * T2_];      // relu(conv3(keys'))
__device__ float g_k  [B_ * CATT * T2_];      // final k
__device__ float g_q1 [B_ * 160 * T1_];       // relu(conv3(queries'))
__device__ float g_q2l[B_ * 80  * T1_];       // relu(1x1)
__device__ float g_q  [B_ * CATT * T1_];      // final q
__device__ float g_k2s[B_ * T2_];
__device__ float g_q2s[B_ * T1_];

// ---------------- speaker projection: out[b,co] = se[b]·W[co] + bias[co] ----------------
__global__ void bias_proj_kernel(const float* __restrict__ se, const float* __restrict__ W,
                                 const float* __restrict__ bias, float* __restrict__ out,
                                 int Cin, int Cout)
{
    int b    = blockIdx.y;
    int co   = blockIdx.x * 8 + (threadIdx.x >> 5);
    int lane = threadIdx.x & 31;
    if (co >= Cout) return;
    const float* s = se + (size_t)b * Cin;
    const float* w = W  + (size_t)co * Cin;
    float acc = 0.f;
    for (int i = lane; i < Cin; i += 32) acc += s[i] * w[i];
    #pragma unroll
    for (int o = 16; o > 0; o >>= 1) acc += __shfl_xor_sync(0xffffffffu, acc, o);
    if (lane == 0) out[b * Cout + co] = acc + bias[co];
}

// ---------------- conv1d k=3, pad=1, input gets per-(b,ci) channel bias, optional relu ---
// block: 256 threads, tile 64(co) x 64(t), 4x4 per thread, K chunked by 16 channels
#define CI_CH 16
__global__ void conv3_kernel(const float* __restrict__ x, const float* __restrict__ chb,
                             const float* __restrict__ W, const float* __restrict__ bias,
                             float* __restrict__ y,
                             int Cin, int Cout, int T, int relu)
{
    __shared__ float Xs[CI_CH][68];        // input halo tile [ci][t0-1 .. t0+64]
    __shared__ float Ws[CI_CH * 3][65];    // [ci*3+d][co]

    const int b   = blockIdx.z;
    const int co0 = blockIdx.y * 64;
    const int t0  = blockIdx.x * 64;
    const int tx  = threadIdx.x & 15;
    const int ty  = threadIdx.x >> 4;

    float acc[4][4];
    #pragma unroll
    for (int i = 0; i < 4; i++)
        #pragma unroll
        for (int j = 0; j < 4; j++) acc[i][j] = 0.f;

    const float* xb = x + (size_t)b * Cin * T;

    for (int ci0 = 0; ci0 < Cin; ci0 += CI_CH) {
        // stage input tile (+channel bias, zero-pad outside [0,T))
        for (int idx = threadIdx.x; idx < CI_CH * 66; idx += 256) {
            int ci = idx / 66, tt = idx % 66;
            int tg = t0 - 1 + tt;
            float v = 0.f;
            if (tg >= 0 && tg < T)
                v = xb[(size_t)(ci0 + ci) * T + tg] + chb[b * Cin + ci0 + ci];
            Xs[ci][tt] = v;
        }
        // stage weights: 48 contiguous floats per co (coalesced runs)
        for (int idx = threadIdx.x; idx < 64 * 48; idx += 256) {
            int co = idx / 48, kk = idx % 48;
            int cog = co0 + co;
            float v = 0.f;
            if (cog < Cout) v = W[(size_t)cog * Cin * 3 + (size_t)ci0 * 3 + kk];
            Ws[kk][co] = v;
        }
        __syncthreads();

        #pragma unroll
        for (int ci = 0; ci < CI_CH; ci++) {
            #pragma unroll
            for (int d = 0; d < 3; d++) {
                const int kk = ci * 3 + d;
                float a0 = Ws[kk][ty];
                float a1 = Ws[kk][ty + 16];
                float a2 = Ws[kk][ty + 32];
                float a3 = Ws[kk][ty + 48];
                float b0 = Xs[ci][tx + d];
                float b1 = Xs[ci][tx + 16 + d];
                float b2 = Xs[ci][tx + 32 + d];
                float b3 = Xs[ci][tx + 48 + d];
                acc[0][0] += a0 * b0; acc[0][1] += a0 * b1; acc[0][2] += a0 * b2; acc[0][3] += a0 * b3;
                acc[1][0] += a1 * b0; acc[1][1] += a1 * b1; acc[1][2] += a1 * b2; acc[1][3] += a1 * b3;
                acc[2][0] += a2 * b0; acc[2][1] += a2 * b1; acc[2][2] += a2 * b2; acc[2][3] += a2 * b3;
                acc[3][0] += a3 * b0; acc[3][1] += a3 * b1; acc[3][2] += a3 * b2; acc[3][3] += a3 * b3;
            }
        }
        __syncthreads();
    }

    #pragma unroll
    for (int i = 0; i < 4; i++) {
        int co = co0 + ty + 16 * i;
        if (co >= Cout) continue;
        float bv = bias[co];
        #pragma unroll
        for (int j = 0; j < 4; j++) {
            int t = t0 + tx + 16 * j;
            if (t >= T) continue;
            float v = acc[i][j] + bv;
            if (relu) v = fmaxf(v, 0.f);
            y[((size_t)b * Cout + co) * T + t] = v;
        }
    }
}

// ---------------- 1x1 conv (GEMM), Cout<=80, tile 80(co) x 64(t), 5x4 per thread ------
__global__ void conv1x1_kernel(const float* __restrict__ x, const float* __restrict__ W,
                               const float* __restrict__ bias, float* __restrict__ y,
                               int Cin, int Cout, int T, int relu)
{
    __shared__ float Xs[CI_CH][66];
    __shared__ float Ws[CI_CH][81];

    const int b  = blockIdx.y;
    const int t0 = blockIdx.x * 64;
    const int tx = threadIdx.x & 15;
    const int ty = threadIdx.x >> 4;

    float acc[5][4];
    #pragma unroll
    for (int i = 0; i < 5; i++)
        #pragma unroll
        for (int j = 0; j < 4; j++) acc[i][j] = 0.f;

    const float* xb = x + (size_t)b * Cin * T;

    for (int ci0 = 0; ci0 < Cin; ci0 += CI_CH) {
        for (int idx = threadIdx.x; idx < CI_CH * 64; idx += 256) {
            int ci = idx >> 6, tt = idx & 63;
            int tg = t0 + tt;
            Xs[ci][tt] = (tg < T) ? xb[(size_t)(ci0 + ci) * T + tg] : 0.f;
        }
        for (int idx = threadIdx.x; idx < 80 * CI_CH; idx += 256) {
            int co = idx >> 4, ci = idx & 15;
            float v = 0.f;
            if (co < Cout) v = W[(size_t)co * Cin + ci0 + ci];
            Ws[ci][co] = v;
        }
        __syncthreads();

        #pragma unroll
        for (int ci = 0; ci < CI_CH; ci++) {
            float a0 = Ws[ci][ty];
            float a1 = Ws[ci][ty + 16];
            float a2 = Ws[ci][ty + 32];
            float a3 = Ws[ci][ty + 48];
            float a4 = Ws[ci][ty + 64];
            float b0 = Xs[ci][tx];
            float b1 = Xs[ci][tx + 16];
            float b2 = Xs[ci][tx + 32];
            float b3 = Xs[ci][tx + 48];
            acc[0][0] += a0 * b0; acc[0][1] += a0 * b1; acc[0][2] += a0 * b2; acc[0][3] += a0 * b3;
            acc[1][0] += a1 * b0; acc[1][1] += a1 * b1; acc[1][2] += a1 * b2; acc[1][3] += a1 * b3;
            acc[2][0] += a2 * b0; acc[2][1] += a2 * b1; acc[2][2] += a2 * b2; acc[2][3] += a2 * b3;
            acc[3][0] += a3 * b0; acc[3][1] += a3 * b1; acc[3][2] += a3 * b2; acc[3][3] += a3 * b3;
            acc[4][0] += a4 * b0; acc[4][1] += a4 * b1; acc[4][2] += a4 * b2; acc[4][3] += a4 * b3;
        }
        __syncthreads();
    }

    #pragma unroll
    for (int i = 0; i < 5; i++) {
        int co = ty + 16 * i;
        if (co >= Cout) continue;
        float bv = bias[co];
        #pragma unroll
        for (int j = 0; j < 4; j++) {
            int t = t0 + tx + 16 * j;
            if (t >= T) continue;
            float v = acc[i][j] + bv;
            if (relu) v = fmaxf(v, 0.f);
            y[((size_t)b * Cout + co) * T + t] = v;
        }
    }
}

// ---------------- per-position sum of squares over channels ----------------
__global__ void sumsq_kernel(const float* __restrict__ x, float* __restrict__ out, int C, int T)
{
    int b = blockIdx.y;
    int t = blockIdx.x * 256 + threadIdx.x;
    if (t >= T) return;
    const float* xb = x + (size_t)b * C * T;
    float s = 0.f;
    for (int c = 0; c < C; c++) {
        float v = xb[(size_t)c * T + t];
        s += v * v;
    }
    out[b * T + t] = s;
}

// ---------------- fused qk + distance + log_softmax + masked softmax ----------------
// grid (T1/32, B), 256 threads. Warp w owns rows t0+4w..t0+4w+3 (s = lane+32*j).
__global__ void attn_kernel(const float* __restrict__ q, const float* __restrict__ k,
                            const float* __restrict__ q2s, const float* __restrict__ k2s,
                            const float* __restrict__ prior, const int* __restrict__ msk_in,
                            float* __restrict__ attn_out, float* __restrict__ logp_out)
{
    extern __shared__ float Ks[];          // [80][404]
    __shared__ float Qs[80][33];

    const int b   = blockIdx.y;
    const int t0  = blockIdx.x * 32;
    const int tid = threadIdx.x;

    const float* kb = k + (size_t)b * 80 * 400;
    for (int idx = tid; idx < 80 * 400; idx += 256) {
        int c = idx / 400, s = idx - c * 400;
        Ks[c * 404 + s] = kb[idx];
    }
    const float* qb = q + (size_t)b * 80 * 1600;
    for (int idx = tid; idx < 80 * 32; idx += 256) {
        int c = idx >> 5, tt = idx & 31;
        Qs[c][tt] = qb[(size_t)c * 1600 + t0 + tt];
    }
    __syncthreads();

    const int lane = tid & 31;
    const int w    = tid >> 5;
    const float NINF = __int_as_float(0xff800000u);

    float acc[4][13];
    #pragma unroll
    for (int r = 0; r < 4; r++)
        #pragma unroll
        for (int j = 0; j < 13; j++) acc[r][j] = 0.f;

    #pragma unroll 4
    for (int c = 0; c < 80; c++) {
        float kv[13];
        #pragma unroll
        for (int j = 0; j < 13; j++) {
            int s = lane + 32 * j;
            kv[j] = (s < 400) ? Ks[c * 404 + s] : 0.f;
        }
        float qv[4];
        #pragma unroll
        for (int r = 0; r < 4; r++) qv[r] = Qs[c][w * 4 + r];
        #pragma unroll
        for (int r = 0; r < 4; r++)
            #pragma unroll
            for (int j = 0; j < 13; j++)
                acc[r][j] += qv[r] * kv[j];
    }

    float k2v[13];
    int   mskv[13];
    #pragma unroll
    for (int j = 0; j < 13; j++) {
        int s = lane + 32 * j;
        k2v[j] = (s < 400) ? k2s[b * 400 + s] : 0.f;
        mskv[j] = (s < 400) ? msk_in[b * 400 + s] : 1;   // bool serialized as int32
    }

    #pragma unroll
    for (int r = 0; r < 4; r++) {
        const int t   = t0 + w * 4 + r;
        const float q2v = q2s[b * 1600 + t];

        float x[13];
        float mx = NINF;
        #pragma unroll
        for (int j = 0; j < 13; j++) {
            int s = lane + 32 * j;
            x[j] = (s < 400) ? (-TEMP * (q2v + k2v[j] - 2.f * acc[r][j])) : NINF;
            mx = fmaxf(mx, x[j]);
        }
        #pragma unroll
        for (int o = 16; o > 0; o >>= 1) mx = fmaxf(mx, __shfl_xor_sync(0xffffffffu, mx, o));
        float se = 0.f;
        #pragma unroll
        for (int j = 0; j < 13; j++) se += expf(x[j] - mx);
        #pragma unroll
        for (int o = 16; o > 0; o >>= 1) se += __shfl_xor_sync(0xffffffffu, se, o);
        const float lse = logf(se) + mx;

        const float* pr  = prior    + ((size_t)b * 1600 + t) * 400;
        float* lp_out    = logp_out + ((size_t)b * 1600 + t) * 400;
        float* at_out    = attn_out + ((size_t)b * 1600 + t) * 400;

        float y[13];
        float mx2 = NINF;
        #pragma unroll
        for (int j = 0; j < 13; j++) {
            int s = lane + 32 * j;
            if (s < 400) {
                float lp = x[j] - lse + logf(pr[s] + 1e-8f);
                lp_out[s] = lp;
                y[j] = mskv[j] ? NINF : lp;
            } else {
                y[j] = NINF;
            }
            mx2 = fmaxf(mx2, y[j]);
        }
        #pragma unroll
        for (int o = 16; o > 0; o >>= 1) mx2 = fmaxf(mx2, __shfl_xor_sync(0xffffffffu, mx2, o));
        float s2 = 0.f;
        #pragma unroll
        for (int j = 0; j < 13; j++) {
            float e = expf(y[j] - mx2);
            y[j] = e;
            s2 += e;
        }
        #pragma unroll
        for (int o = 16; o > 0; o >>= 1) s2 += __shfl_xor_sync(0xffffffffu, s2, o);
        const float inv = 1.f / s2;
        #pragma unroll
        for (int j = 0; j < 13; j++) {
            int s = lane + 32 * j;
            if (s < 400) at_out[s] = y[j] * inv;
        }
    }
}

// ---------------- launch ----------------
extern "C" void kernel_launch(void* const* d_in, const int* in_sizes, int n_in,
                              void* d_out, int out_size)
{
    const float* queries = (const float*)d_in[0];
    const float* keys    = (const float*)d_in[1];
    const int*   mask    = (const int*)d_in[2];     // bool -> int32 in harness
    const float* prior   = (const float*)d_in[3];
    const float* se      = (const float*)d_in[4];
    const float* Wk1     = (const float*)d_in[5];
    const float* bk1     = (const float*)d_in[6];
    const float* Wk2     = (const float*)d_in[7];
    const float* bk2     = (const float*)d_in[8];
    const float* Wq1     = (const float*)d_in[9];
    const float* bq1     = (const float*)d_in[10];
    const float* Wq2     = (const float*)d_in[11];
    const float* bq2     = (const float*)d_in[12];
    const float* Wq3     = (const float*)d_in[13];
    const float* bq3     = (const float*)d_in[14];
    const float* Wks     = (const float*)d_in[15];
    const float* bks     = (const float*)d_in[16];
    const float* Wqs     = (const float*)d_in[17];
    const float* bqs     = (const float*)d_in[18];
    float* out = (float*)d_out;

    float *kb, *qb, *k1, *kf, *q1, *q2l, *qf, *k2s, *q2s;
    cudaGetSymbolAddress((void**)&kb,  g_kb);
    cudaGetSymbolAddress((void**)&qb,  g_qb);
    cudaGetSymbolAddress((void**)&k1,  g_k1);
    cudaGetSymbolAddress((void**)&kf,  g_k);
    cudaGetSymbolAddress((void**)&q1,  g_q1);
    cudaGetSymbolAddress((void**)&q2l, g_q2l);
    cudaGetSymbolAddress((void**)&qf,  g_q);
    cudaGetSymbolAddress((void**)&k2s, g_k2s);
    cudaGetSymbolAddress((void**)&q2s, g_q2s);

    float* attn_out = out;
    float* logp_out = out + (size_t)B_ * T1_ * T2_;

    // speaker projections
    bias_proj_kernel<<<dim3(CTXT / 8, B_), 256>>>(se, Wks, bks, kb, CTXT, CTXT);
    bias_proj_kernel<<<dim3((CMEL + 7) / 8, B_), 256>>>(se, Wqs, bqs, qb, CTXT, CMEL);

    // key path
    conv3_kernel<<<dim3((T2_ + 63) / 64, 1024 / 64, B_), 256>>>(keys, kb, Wk1, bk1, k1, CTXT, 1024, T2_, 1);
    conv1x1_kernel<<<dim3((T2_ + 63) / 64, B_), 256>>>(k1, Wk2, bk2, kf, 1024, CATT, T2_, 0);

    // query path
    conv3_kernel<<<dim3((T1_ + 63) / 64, (160 + 63) / 64, B_), 256>>>(queries, qb, Wq1, bq1, q1, CMEL, 160, T1_, 1);
    conv1x1_kernel<<<dim3((T1_ + 63) / 64, B_), 256>>>(q1, Wq2, bq2, q2l, 160, 80, T1_, 1);
    conv1x1_kernel<<<dim3((T1_ + 63) / 64, B_), 256>>>(q2l, Wq3, bq3, qf, 80, 80, T1_, 0);

    // norms
    sumsq_kernel<<<dim3((T2_ + 255) / 256, B_), 256>>>(kf, k2s, CATT, T2_);
    sumsq_kernel<<<dim3((T1_ + 255) / 256, B_), 256>>>(qf, q2s, CATT, T1_);

    // fused attention epilogue
    const int ks_bytes = 80 * 404 * sizeof(float);
    cudaFuncSetAttribute(attn_kernel, cudaFuncAttributeMaxDynamicSharedMemorySize, ks_bytes);
    attn_kernel<<<dim3(T1_ / 32, B_), 256, ks_bytes>>>(qf, kf, q2s, k2s, prior, mask, attn_out, logp_out);
}

// round 4
// speedup vs baseline: 2.5808x; 2.5808x over previous
#include <cuda_runtime.h>
#include <cuda_bf16.h>
#include <cstdint>
#include <math.h>

#define TEMP 0.0005f
#define B_   32
#define CMEL 80
#define CTXT 512
#define CATT 80
#define T1_  1600
#define T2_  400

// ---------------- scratch (device globals; no allocation) ----------------
__device__ float g_kb [B_ * CTXT];            // speaker bias for keys
__device__ float g_qb [B_ * CMEL];            // speaker bias for queries
__device__ float g_k1 [B_ * 1024 * T2_];      // relu(conv3(keys'))
__device__ float g_k  [B_ * CATT * T2_];      // final k
__device__ float g_q1 [B_ * 160 * T1_];       // relu(conv3(queries'))
__device__ float g_q2l[B_ * 80  * T1_];       // relu(1x1)
__device__ float g_q  [B_ * CATT * T1_];      // final q
__device__ float g_k2s[B_ * T2_];
__device__ float g_q2s[B_ * T1_];

// ---------------- speaker projection ----------------
__global__ void bias_proj_kernel(const float* __restrict__ se, const float* __restrict__ W,
                                 const float* __restrict__ bias, float* __restrict__ out,
                                 int Cin, int Cout)
{
    int b    = blockIdx.y;
    int co   = blockIdx.x * 8 + (threadIdx.x >> 5);
    int lane = threadIdx.x & 31;
    if (co >= Cout) return;
    const float* s = se + (size_t)b * Cin;
    const float* w = W  + (size_t)co * Cin;
    float acc = 0.f;
    for (int i = lane; i < Cin; i += 32) acc += s[i] * w[i];
    #pragma unroll
    for (int o = 16; o > 0; o >>= 1) acc += __shfl_xor_sync(0xffffffffu, acc, o);
    if (lane == 0) out[b * Cout + co] = acc + bias[co];
}

// ---------------- bf16 tensor-core conv GEMM ----------------
__device__ __forceinline__ uint32_t smem_u32(const void* p) {
    return (uint32_t)__cvta_generic_to_shared(p);
}
__device__ __forceinline__ void ldsm_x4(uint32_t* r, uint32_t addr) {
    asm volatile("ldmatrix.sync.aligned.m8n8.x4.shared.b16 {%0,%1,%2,%3}, [%4];"
                 : "=r"(r[0]), "=r"(r[1]), "=r"(r[2]), "=r"(r[3]) : "r"(addr));
}
__device__ __forceinline__ void ldsm_x4_t(uint32_t* r, uint32_t addr) {
    asm volatile("ldmatrix.sync.aligned.m8n8.x4.trans.shared.b16 {%0,%1,%2,%3}, [%4];"
                 : "=r"(r[0]), "=r"(r[1]), "=r"(r[2]), "=r"(r[3]) : "r"(addr));
}
__device__ __forceinline__ void mma_bf16(float* c, const uint32_t* a, const uint32_t* b) {
    asm volatile("mma.sync.aligned.m16n8k16.row.col.f32.bf16.bf16.f32 "
                 "{%0,%1,%2,%3}, {%4,%5,%6,%7}, {%8,%9}, {%0,%1,%2,%3};"
                 : "+f"(c[0]), "+f"(c[1]), "+f"(c[2]), "+f"(c[3])
                 : "r"(a[0]), "r"(a[1]), "r"(a[2]), "r"(a[3]), "r"(b[0]), "r"(b[1]));
}

// y[b,co,t] = sum_{ci,d} W[co, ci*KW+d] * (x[b,ci,t+d-(KW>>1)] + chb[b,ci])  (+bias, relu)
// A = W row-major [co][K] (K = Cin*KW), B = im2col rows [k][t].
// Block tile: 64co x 64t, 8 warps (2x4), warp 32x16, K chunks of 16, reg prefetch.
template<int KW, bool RELU, bool CHB>
__global__ __launch_bounds__(256)
void mma_conv_kernel(const float* __restrict__ x, const float* __restrict__ chb,
                     const float* __restrict__ W, const float* __restrict__ bias,
                     float* __restrict__ y, int Cin, int Cout, int T)
{
    const int K  = Cin * KW;           // always a multiple of 16 here
    const int NK = K >> 4;

    __shared__ __align__(16) __nv_bfloat16 As[64][24];   // [co][k] pitch 48B
    __shared__ __align__(16) __nv_bfloat16 Bs[16][72];   // [k][t]  pitch 144B

    const int b    = blockIdx.z;
    const int co0  = blockIdx.y * 64;
    const int t0   = blockIdx.x * 64;
    const int tid  = threadIdx.x;
    const int lane = tid & 31;
    const int wid  = tid >> 5;
    const int wm   = wid >> 2;     // 0..1
    const int wn   = wid & 3;      // 0..3

    // staging assignment
    const int aco = tid >> 2;            // 0..63
    const int akb = (tid & 3) << 2;      // 0,4,8,12
    const int bkk = tid >> 4;            // 0..15
    const int btb = (tid & 15) << 2;     // 0,4,...,60
    const bool aok = (co0 + aco) < Cout;
    const float* wp = W + (size_t)(co0 + aco) * K + akb;

    float4 av = make_float4(0.f, 0.f, 0.f, 0.f);
    float  bv[4];

    // prefetch chunk 0
    if (aok) av = *(const float4*)(wp);
    {
        int k  = bkk;
        int ci = (KW == 1) ? k : (k / 3);
        int d  = (KW == 1) ? 0 : (k % 3);
        const float* xr = x + ((size_t)b * Cin + ci) * T;
        float ca = CHB ? chb[b * Cin + ci] : 0.f;
        #pragma unroll
        for (int j = 0; j < 4; j++) {
            int tg = t0 + btb + j + d - (KW >> 1);
            bv[j] = (tg >= 0 && tg < T) ? (xr[tg] + ca) : 0.f;
        }
    }

    float acc[2][2][4];
    #pragma unroll
    for (int i = 0; i < 2; i++)
        #pragma unroll
        for (int j = 0; j < 2; j++)
            #pragma unroll
            for (int r = 0; r < 4; r++) acc[i][j][r] = 0.f;

    const int lrow = lane & 15;
    const int lc8  = (lane >> 4) << 3;
    const uint32_t a_addr0 = smem_u32(&As[wm * 32      + lrow][lc8]);
    const uint32_t a_addr1 = smem_u32(&As[wm * 32 + 16 + lrow][lc8]);
    const uint32_t b_addr  = smem_u32(&Bs[lrow][wn * 16 + lc8]);

    for (int c = 0; c < NK; c++) {
        // commit staged registers to smem (fp32 -> bf16)
        {
            __nv_bfloat162 p0 = __floats2bfloat162_rn(av.x, av.y);
            __nv_bfloat162 p1 = __floats2bfloat162_rn(av.z, av.w);
            uint2 ua; ua.x = *(uint32_t*)&p0; ua.y = *(uint32_t*)&p1;
            *(uint2*)&As[aco][akb] = ua;
            __nv_bfloat162 q0 = __floats2bfloat162_rn(bv[0], bv[1]);
            __nv_bfloat162 q1 = __floats2bfloat162_rn(bv[2], bv[3]);
            uint2 ub; ub.x = *(uint32_t*)&q0; ub.y = *(uint32_t*)&q1;
            *(uint2*)&Bs[bkk][btb] = ub;
        }
        __syncthreads();

        // prefetch next chunk (LDG overlaps the MMAs below)
        if (c + 1 < NK) {
            const int k0 = (c + 1) << 4;
            av = aok ? *(const float4*)(wp + k0) : make_float4(0.f, 0.f, 0.f, 0.f);
            int k  = k0 + bkk;
            int ci = (KW == 1) ? k : (k / 3);
            int d  = (KW == 1) ? 0 : (k % 3);
            const float* xr = x + ((size_t)b * Cin + ci) * T;
            float ca = CHB ? chb[b * Cin + ci] : 0.f;
            #pragma unroll
            for (int j = 0; j < 4; j++) {
                int tg = t0 + btb + j + d - (KW >> 1);
                bv[j] = (tg >= 0 && tg < T) ? (xr[tg] + ca) : 0.f;
            }
        }

        uint32_t afr0[4], afr1[4], bfr[4];
        ldsm_x4(afr0, a_addr0);
        ldsm_x4(afr1, a_addr1);
        ldsm_x4_t(bfr, b_addr);
        mma_bf16(acc[0][0], afr0, bfr);
        mma_bf16(acc[0][1], afr0, bfr + 2);
        mma_bf16(acc[1][0], afr1, bfr);
        mma_bf16(acc[1][1], afr1, bfr + 2);
        __syncthreads();
    }

    // epilogue
    const int g   = lane >> 2;
    const int tg2 = (lane & 3) << 1;
    float* yb = y + (size_t)b * Cout * T;
    #pragma unroll
    for (int mi = 0; mi < 2; mi++) {
        #pragma unroll
        for (int ni = 0; ni < 2; ni++) {
            int row = co0 + wm * 32 + mi * 16 + g;
            int col = t0 + wn * 16 + ni * 8 + tg2;
            if (row < Cout) {
                float bvs = bias[row];
                float v0 = acc[mi][ni][0] + bvs;
                float v1 = acc[mi][ni][1] + bvs;
                if (RELU) { v0 = fmaxf(v0, 0.f); v1 = fmaxf(v1, 0.f); }
                if (col     < T) yb[(size_t)row * T + col]     = v0;
                if (col + 1 < T) yb[(size_t)row * T + col + 1] = v1;
            }
            int row2 = row + 8;
            if (row2 < Cout) {
                float bvs = bias[row2];
                float v2 = acc[mi][ni][2] + bvs;
                float v3 = acc[mi][ni][3] + bvs;
                if (RELU) { v2 = fmaxf(v2, 0.f); v3 = fmaxf(v3, 0.f); }
                if (col     < T) yb[(size_t)row2 * T + col]     = v2;
                if (col + 1 < T) yb[(size_t)row2 * T + col + 1] = v3;
            }
        }
    }
}

// ---------------- per-position sum of squares over channels ----------------
__global__ void sumsq_kernel(const float* __restrict__ x, float* __restrict__ out, int C, int T)
{
    int b = blockIdx.y;
    int t = blockIdx.x * 256 + threadIdx.x;
    if (t >= T) return;
    const float* xb = x + (size_t)b * C * T;
    float s = 0.f;
    for (int c = 0; c < C; c++) {
        float v = xb[(size_t)c * T + t];
        s += v * v;
    }
    out[b * T + t] = s;
}

// ---------------- fused qk + distance + log_softmax + masked softmax ----------------
__global__ void attn_kernel(const float* __restrict__ q, const float* __restrict__ k,
                            const float* __restrict__ q2s, const float* __restrict__ k2s,
                            const float* __restrict__ prior, const int* __restrict__ msk_in,
                            float* __restrict__ attn_out, float* __restrict__ logp_out)
{
    extern __shared__ float Ks[];          // [80][404]
    __shared__ float Qs[80][33];

    const int b   = blockIdx.y;
    const int t0  = blockIdx.x * 32;
    const int tid = threadIdx.x;

    const float* kb = k + (size_t)b * 80 * 400;
    for (int idx = tid; idx < 80 * 400; idx += 256) {
        int c = idx / 400, s = idx - c * 400;
        Ks[c * 404 + s] = kb[idx];
    }
    const float* qb = q + (size_t)b * 80 * 1600;
    for (int idx = tid; idx < 80 * 32; idx += 256) {
        int c = idx >> 5, tt = idx & 31;
        Qs[c][tt] = qb[(size_t)c * 1600 + t0 + tt];
    }
    __syncthreads();

    const int lane = tid & 31;
    const int w    = tid >> 5;
    const float NINF = __int_as_float(0xff800000u);

    float acc[4][13];
    #pragma unroll
    for (int r = 0; r < 4; r++)
        #pragma unroll
        for (int j = 0; j < 13; j++) acc[r][j] = 0.f;

    #pragma unroll 4
    for (int c = 0; c < 80; c++) {
        float kv[13];
        #pragma unroll
        for (int j = 0; j < 13; j++) {
            int s = lane + 32 * j;
            kv[j] = (s < 400) ? Ks[c * 404 + s] : 0.f;
        }
        float qv[4];
        #pragma unroll
        for (int r = 0; r < 4; r++) qv[r] = Qs[c][w * 4 + r];
        #pragma unroll
        for (int r = 0; r < 4; r++)
            #pragma unroll
            for (int j = 0; j < 13; j++)
                acc[r][j] += qv[r] * kv[j];
    }

    float k2v[13];
    int   mskv[13];
    #pragma unroll
    for (int j = 0; j < 13; j++) {
        int s = lane + 32 * j;
        k2v[j] = (s < 400) ? k2s[b * 400 + s] : 0.f;
        mskv[j] = (s < 400) ? msk_in[b * 400 + s] : 1;
    }

    #pragma unroll
    for (int r = 0; r < 4; r++) {
        const int t   = t0 + w * 4 + r;
        const float q2v = q2s[b * 1600 + t];

        float x[13];
        float mx = NINF;
        #pragma unroll
        for (int j = 0; j < 13; j++) {
            int s = lane + 32 * j;
            x[j] = (s < 400) ? (-TEMP * (q2v + k2v[j] - 2.f * acc[r][j])) : NINF;
            mx = fmaxf(mx, x[j]);
        }
        #pragma unroll
        for (int o = 16; o > 0; o >>= 1) mx = fmaxf(mx, __shfl_xor_sync(0xffffffffu, mx, o));
        float se = 0.f;
        #pragma unroll
        for (int j = 0; j < 13; j++) se += expf(x[j] - mx);
        #pragma unroll
        for (int o = 16; o > 0; o >>= 1) se += __shfl_xor_sync(0xffffffffu, se, o);
        const float lse = logf(se) + mx;

        const float* pr  = prior    + ((size_t)b * 1600 + t) * 400;
        float* lp_out    = logp_out + ((size_t)b * 1600 + t) * 400;
        float* at_out    = attn_out + ((size_t)b * 1600 + t) * 400;

        float y[13];
        float mx2 = NINF;
        #pragma unroll
        for (int j = 0; j < 13; j++) {
            int s = lane + 32 * j;
            if (s < 400) {
                float lp = x[j] - lse + logf(pr[s] + 1e-8f);
                lp_out[s] = lp;
                y[j] = mskv[j] ? NINF : lp;
            } else {
                y[j] = NINF;
            }
            mx2 = fmaxf(mx2, y[j]);
        }
        #pragma unroll
        for (int o = 16; o > 0; o >>= 1) mx2 = fmaxf(mx2, __shfl_xor_sync(0xffffffffu, mx2, o));
        float s2 = 0.f;
        #pragma unroll
        for (int j = 0; j < 13; j++) {
            float e = expf(y[j] - mx2);
            y[j] = e;
            s2 += e;
        }
        #pragma unroll
        for (int o = 16; o > 0; o >>= 1) s2 += __shfl_xor_sync(0xffffffffu, s2, o);
        const float inv = 1.f / s2;
        #pragma unroll
        for (int j = 0; j < 13; j++) {
            int s = lane + 32 * j;
            if (s < 400) at_out[s] = y[j] * inv;
        }
    }
}

// ---------------- launch ----------------
extern "C" void kernel_launch(void* const* d_in, const int* in_sizes, int n_in,
                              void* d_out, int out_size)
{
    const float* queries = (const float*)d_in[0];
    const float* keys    = (const float*)d_in[1];
    const int*   mask    = (const int*)d_in[2];     // bool -> int32 in harness
    const float* prior   = (const float*)d_in[3];
    const float* se      = (const float*)d_in[4];
    const float* Wk1     = (const float*)d_in[5];
    const float* bk1     = (const float*)d_in[6];
    const float* Wk2     = (const float*)d_in[7];
    const float* bk2     = (const float*)d_in[8];
    const float* Wq1     = (const float*)d_in[9];
    const float* bq1     = (const float*)d_in[10];
    const float* Wq2     = (const float*)d_in[11];
    const float* bq2     = (const float*)d_in[12];
    const float* Wq3     = (const float*)d_in[13];
    const float* bq3     = (const float*)d_in[14];
    const float* Wks     = (const float*)d_in[15];
    const float* bks     = (const float*)d_in[16];
    const float* Wqs     = (const float*)d_in[17];
    const float* bqs     = (const float*)d_in[18];
    float* out = (float*)d_out;

    float *kb, *qb, *k1, *kf, *q1, *q2l, *qf, *k2s, *q2s;
    cudaGetSymbolAddress((void**)&kb,  g_kb);
    cudaGetSymbolAddress((void**)&qb,  g_qb);
    cudaGetSymbolAddress((void**)&k1,  g_k1);
    cudaGetSymbolAddress((void**)&kf,  g_k);
    cudaGetSymbolAddress((void**)&q1,  g_q1);
    cudaGetSymbolAddress((void**)&q2l, g_q2l);
    cudaGetSymbolAddress((void**)&qf,  g_q);
    cudaGetSymbolAddress((void**)&k2s, g_k2s);
    cudaGetSymbolAddress((void**)&q2s, g_q2s);

    float* attn_out = out;
    float* logp_out = out + (size_t)B_ * T1_ * T2_;

    // speaker projections
    bias_proj_kernel<<<dim3(CTXT / 8, B_), 256>>>(se, Wks, bks, kb, CTXT, CTXT);
    bias_proj_kernel<<<dim3((CMEL + 7) / 8, B_), 256>>>(se, Wqs, bqs, qb, CTXT, CMEL);

    // key path (tensor cores)
    mma_conv_kernel<3, true,  true ><<<dim3((T2_ + 63) / 64, 1024 / 64, B_), 256>>>(keys, kb, Wk1, bk1, k1, CTXT, 1024, T2_);
    mma_conv_kernel<1, false, false><<<dim3((T2_ + 63) / 64, 2,         B_), 256>>>(k1, nullptr, Wk2, bk2, kf, 1024, CATT, T2_);

    // query path (tensor cores)
    mma_conv_kernel<3, true,  true ><<<dim3((T1_ + 63) / 64, 3,         B_), 256>>>(queries, qb, Wq1, bq1, q1, CMEL, 160, T1_);
    mma_conv_kernel<1, true,  false><<<dim3((T1_ + 63) / 64, 2,         B_), 256>>>(q1, nullptr, Wq2, bq2, q2l, 160, 80, T1_);
    mma_conv_kernel<1, false, false><<<dim3((T1_ + 63) / 64, 2,         B_), 256>>>(q2l, nullptr, Wq3, bq3, qf, 80, 80, T1_);

    // norms
    sumsq_kernel<<<dim3((T2_ + 255) / 256, B_), 256>>>(kf, k2s, CATT, T2_);
    sumsq_kernel<<<dim3((T1_ + 255) / 256, B_), 256>>>(qf, q2s, CATT, T1_);

    // fused attention epilogue
    const int ks_bytes = 80 * 404 * sizeof(float);
    cudaFuncSetAttribute(attn_kernel, cudaFuncAttributeMaxDynamicSharedMemorySize, ks_bytes);
    attn_kernel<<<dim3(T1_ / 32, B_), 256, ks_bytes>>>(qf, kf, q2s, k2s, prior, mask, attn_out, logp_out);
}

// round 6
// speedup vs baseline: 4.5631x; 1.7681x over previous
#include <cuda_runtime.h>
#include <cuda_bf16.h>
#include <cstdint>
#include <math.h>

#define TEMP 0.0005f
#define B_   32
#define CMEL 80
#define CTXT 512
#define CATT 80
#define T1_  1600
#define T2_  400

typedef __nv_bfloat16 bf16;

// ---------------- scratch (device globals; no allocation) ----------------
__device__ float g_kb [B_ * CTXT];
__device__ float g_qb [B_ * CMEL];
__device__ bf16  g_keys3[3u * B_ * CTXT * T2_];   // shifted biased keys
__device__ bf16  g_que3 [3u * B_ * CMEL * T1_];   // shifted biased queries
__device__ bf16  g_pWk1[1024 * 1536];
__device__ bf16  g_pWk2[80 * 1024];
__device__ bf16  g_pWq1[160 * 240];
__device__ bf16  g_pWq2[80 * 160];
__device__ bf16  g_pWq3[80 * 80];
__device__ bf16  g_k1b[(size_t)B_ * 1024 * T2_];
__device__ bf16  g_q1b[(size_t)B_ * 160 * T1_];
__device__ bf16  g_q2b[(size_t)B_ * 80 * T1_];
__device__ bf16  g_kfb[(size_t)B_ * CATT * T2_];
__device__ float g_q  [(size_t)B_ * CATT * T1_];
__device__ float g_k2s[B_ * T2_];
__device__ float g_q2s[B_ * T1_];

// ---------------- speaker projection ----------------
__global__ void bias_proj_kernel(const float* __restrict__ se, const float* __restrict__ W,
                                 const float* __restrict__ bias, float* __restrict__ out,
                                 int Cin, int Cout)
{
    int b    = blockIdx.y;
    int co   = blockIdx.x * 8 + (threadIdx.x >> 5);
    int lane = threadIdx.x & 31;
    if (co >= Cout) return;
    const float* s = se + (size_t)b * Cin;
    const float* w = W  + (size_t)co * Cin;
    float acc = 0.f;
    for (int i = lane; i < Cin; i += 32) acc += s[i] * w[i];
    #pragma unroll
    for (int o = 16; o > 0; o >>= 1) acc += __shfl_xor_sync(0xffffffffu, acc, o);
    if (lane == 0) out[b * Cout + co] = acc + bias[co];
}

// ---------------- prep: pack weights ----------------
__global__ void pack_w3_kernel(const float* __restrict__ W, bf16* __restrict__ out,
                               int Cout, int Cin)
{
    int i = blockIdx.x * 256 + threadIdx.x;
    int n = Cout * Cin * 3;
    if (i >= n) return;
    int co = i / (Cin * 3), r = i - co * Cin * 3;
    int ci = r / 3, d = r - ci * 3;
    out[(size_t)co * Cin * 3 + d * Cin + ci] = __float2bfloat16(W[i]);
}

__global__ void pack_w1_kernel(const float* __restrict__ W, bf16* __restrict__ out, int n)
{
    int i = blockIdx.x * 256 + threadIdx.x;
    if (i < n) out[i] = __float2bfloat16(W[i]);
}

// ---------------- prep: biased + shifted inputs (3 taps) ----------------
// out[d][b][c][t] = bf16(x[b][c][t + d - 1] + chb[b][c]), zero outside [0,T)
__global__ void prep_x3_kernel(const float* __restrict__ x, const float* __restrict__ chb,
                               bf16* __restrict__ out, int Cin, int T)
{
    int bc = blockIdx.y;
    int b  = bc / Cin;
    int t  = blockIdx.x * 256 + threadIdx.x;
    if (t >= T) return;
    float  ca = chb[bc];                  // chb laid out [b][Cin]
    float  v  = x[(size_t)bc * T + t] + ca;
    bf16   bv = __float2bfloat16(v);
    size_t plane = (size_t)B_ * Cin * T;
    size_t base  = (size_t)bc * T;
    out[plane + base + t] = bv;                           // d=1 (center)
    if (t + 1 < T) out[base + t + 1] = bv;                // d=0 (reads t-1)
    if (t == 0)     out[base + 0] = __float2bfloat16(0.f);
    if (t >= 1)     out[2 * plane + base + t - 1] = bv;   // d=2 (reads t+1)
    if (t == T - 1) out[2 * plane + base + T - 1] = __float2bfloat16(0.f);
}

// ---------------- MMA helpers ----------------
__device__ __forceinline__ uint32_t smem_u32(const void* p) {
    return (uint32_t)__cvta_generic_to_shared(p);
}
__device__ __forceinline__ void ldsm_x4(uint32_t* r, uint32_t addr) {
    asm volatile("ldmatrix.sync.aligned.m8n8.x4.shared.b16 {%0,%1,%2,%3}, [%4];"
                 : "=r"(r[0]), "=r"(r[1]), "=r"(r[2]), "=r"(r[3]) : "r"(addr));
}
__device__ __forceinline__ void ldsm_x4_t(uint32_t* r, uint32_t addr) {
    asm volatile("ldmatrix.sync.aligned.m8n8.x4.trans.shared.b16 {%0,%1,%2,%3}, [%4];"
                 : "=r"(r[0]), "=r"(r[1]), "=r"(r[2]), "=r"(r[3]) : "r"(addr));
}
__device__ __forceinline__ void mma_bf16(float* c, const uint32_t* a, const uint32_t* b) {
    asm volatile("mma.sync.aligned.m16n8k16.row.col.f32.bf16.bf16.f32 "
                 "{%0,%1,%2,%3}, {%4,%5,%6,%7}, {%8,%9}, {%0,%1,%2,%3};"
                 : "+f"(c[0]), "+f"(c[1]), "+f"(c[2]), "+f"(c[3])
                 : "r"(a[0]), "r"(a[1]), "r"(a[2]), "r"(a[3]), "r"(b[0]), "r"(b[1]));
}
__device__ __forceinline__ void cp16(void* sdst, const void* gsrc, int sz) {
    asm volatile("cp.async.cg.shared.global [%0], [%1], 16, %2;"
                 :: "r"(smem_u32(sdst)), "l"(gsrc), "r"(sz) : "memory");
}

// ---------------- bf16 GEMM: Y[b,co,t] = sum_k A[co,k] * Brow_k[t] (+bias, relu) -------
// A: [Cout][Ktot] bf16.  X: TAPS==1 -> [B][Ktot][T]; TAPS==3 -> [3][B][Cin][T].
// Tile 64co x 128t, K-chunk 32, 2-stage cp.async. 8 warps = 2(m) x 4(n), warp 32x32.
template<int TAPS, bool RELU, bool OUT_BF16>
__global__ __launch_bounds__(256)
void gemm_conv_kernel(const bf16* __restrict__ A, const bf16* __restrict__ X,
                      const float* __restrict__ bias, void* __restrict__ Y,
                      int Cin, int Cout, int Ktot, int T)
{
    __shared__ __align__(16) bf16 As[2][64][40];    // 80B pitch, conflict-free ldsm
    __shared__ __align__(16) bf16 Bs[2][32][136];   // 272B pitch, conflict-free ldsm

    const int b   = blockIdx.z;
    const int co0 = blockIdx.y * 64;
    const int t0  = blockIdx.x * 128;
    const int tid = threadIdx.x;
    const int lane = tid & 31, wid = tid >> 5;
    const int wm = wid >> 2, wn = wid & 3;
    const int NC = (Ktot + 31) >> 5;

    const int a_row = tid >> 2;
    const int a_seg = (tid & 3) << 3;

    auto stage = [&](int c, int buf) {
        const int k0 = c << 5;
        {   // A: 1 x 16B per thread
            int kk = k0 + a_seg;
            const bf16* src = A;
            int sz = 0;
            if ((co0 + a_row) < Cout && kk < Ktot) {
                src = A + (size_t)(co0 + a_row) * Ktot + kk;
                sz = 16;
            }
            cp16(&As[buf][a_row][a_seg], src, sz);
        }
        #pragma unroll
        for (int i = 0; i < 2; i++) {   // B: 2 x 16B per thread
            int u = tid + (i << 8);
            int krow = u >> 4;
            int tseg = (u & 15) << 3;
            int k  = k0 + krow;
            int tg = t0 + tseg;
            const bf16* src = X;
            int sz = 0;
            if (k < Ktot && tg < T) {
                if (TAPS == 3) {
                    int d  = (k >= 2 * Cin) ? 2 : ((k >= Cin) ? 1 : 0);
                    int ci = k - d * Cin;
                    src = X + ((size_t)(d * B_ + b) * Cin + ci) * T + tg;
                } else {
                    src = X + ((size_t)b * Cin + k) * T + tg;
                }
                sz = 16;
            }
            cp16(&Bs[buf][krow][tseg], src, sz);
        }
        asm volatile("cp.async.commit_group;" ::: "memory");
    };

    float acc[2][4][4];
    #pragma unroll
    for (int m = 0; m < 2; m++)
        #pragma unroll
        for (int n = 0; n < 4; n++)
            #pragma unroll
            for (int r = 0; r < 4; r++) acc[m][n][r] = 0.f;

    const int lr = lane & 15, lh = lane >> 4;
    const uint32_t a_base = smem_u32(&As[0][wm * 32 + lr][lh * 8]);
    const uint32_t b_base = smem_u32(&Bs[0][lr][wn * 32 + lh * 8]);
    const uint32_t ABUF = 64 * 40 * 2;
    const uint32_t BBUF = 32 * 136 * 2;

    stage(0, 0);
    for (int c = 0; c < NC; c++) {
        const int buf = c & 1;
        if (c + 1 < NC) {
            stage(c + 1, buf ^ 1);
            asm volatile("cp.async.wait_group 1;" ::: "memory");
        } else {
            asm volatile("cp.async.wait_group 0;" ::: "memory");
        }
        __syncthreads();

        #pragma unroll
        for (int k16 = 0; k16 < 32; k16 += 16) {
            uint32_t aaddr = a_base + buf * ABUF + k16 * 2;
            uint32_t baddr = b_base + buf * BBUF + k16 * 272;
            uint32_t af0[4], af1[4], bf0[4], bf1[4];
            ldsm_x4(af0, aaddr);
            ldsm_x4(af1, aaddr + 16 * 80);
            ldsm_x4_t(bf0, baddr);
            ldsm_x4_t(bf1, baddr + 32);
            mma_bf16(acc[0][0], af0, bf0);
            mma_bf16(acc[0][1], af0, bf0 + 2);
            mma_bf16(acc[0][2], af0, bf1);
            mma_bf16(acc[0][3], af0, bf1 + 2);
            mma_bf16(acc[1][0], af1, bf0);
            mma_bf16(acc[1][1], af1, bf0 + 2);
            mma_bf16(acc[1][2], af1, bf1);
            mma_bf16(acc[1][3], af1, bf1 + 2);
        }
        __syncthreads();
    }

    // epilogue
    const int g   = lane >> 2;
    const int c2  = (lane & 3) << 1;
    #pragma unroll
    for (int m = 0; m < 2; m++) {
        #pragma unroll
        for (int n = 0; n < 4; n++) {
            int row = co0 + wm * 32 + m * 16 + g;
            int col = t0 + wn * 32 + n * 8 + c2;
            #pragma unroll
            for (int h = 0; h < 2; h++) {   // h=0: rows g, h=1: rows g+8
                int rr = row + h * 8;
                if (rr >= Cout || col >= T) continue;
                float bvs = bias[rr];
                float v0 = acc[m][n][h * 2 + 0] + bvs;
                float v1 = acc[m][n][h * 2 + 1] + bvs;
                if (RELU) { v0 = fmaxf(v0, 0.f); v1 = fmaxf(v1, 0.f); }
                if (OUT_BF16) {
                    bf16* yb = (bf16*)Y + ((size_t)b * Cout + rr) * T + col;
                    __nv_bfloat162 p = __floats2bfloat162_rn(v0, v1);
                    *(__nv_bfloat162*)yb = p;
                } else {
                    float* yb = (float*)Y + ((size_t)b * Cout + rr) * T + col;
                    yb[0] = v0; yb[1] = v1;
                }
            }
        }
    }
}

// ---------------- sum of squares ----------------
__global__ void sumsq_kernel(const float* __restrict__ x, float* __restrict__ out, int C, int T)
{
    int b = blockIdx.y;
    int t = blockIdx.x * 256 + threadIdx.x;
    if (t >= T) return;
    const float* xb = x + (size_t)b * C * T;
    float s = 0.f;
    for (int c = 0; c < C; c++) {
        float v = xb[(size_t)c * T + t];
        s += v * v;
    }
    out[b * T + t] = s;
}

__global__ void sumsq_bf16_kernel(const bf16* __restrict__ x, float* __restrict__ out, int C, int T)
{
    int b = blockIdx.y;
    int t = blockIdx.x * 256 + threadIdx.x;
    if (t >= T) return;
    const bf16* xb = x + (size_t)b * C * T;
    float s = 0.f;
    for (int c = 0; c < C; c++) {
        float v = __bfloat162float(xb[(size_t)c * T + t]);
        s += v * v;
    }
    out[b * T + t] = s;
}

// ---------------- fused qk + distance + log_softmax + masked softmax ----------------
__global__ void attn_kernel(const float* __restrict__ q, const bf16* __restrict__ kbf,
                            const float* __restrict__ q2s, const float* __restrict__ k2s,
                            const float* __restrict__ prior, const int* __restrict__ msk_in,
                            float* __restrict__ attn_out, float* __restrict__ logp_out)
{
    extern __shared__ bf16 Ks[];           // [80][408]
    __shared__ float Qs[80][33];

    const int b   = blockIdx.y;
    const int t0  = blockIdx.x * 32;
    const int tid = threadIdx.x;

    const bf16* kb_ = kbf + (size_t)b * 80 * 400;
    for (int i8 = tid; i8 < 80 * 50; i8 += 256) {
        int c = i8 / 50, s8 = (i8 - c * 50) * 8;
        *(uint4*)&Ks[c * 408 + s8] = *(const uint4*)&kb_[c * 400 + s8];
    }
    const float* qb = q + (size_t)b * 80 * 1600;
    for (int idx = tid; idx < 80 * 32; idx += 256) {
        int c = idx >> 5, tt = idx & 31;
        Qs[c][tt] = qb[(size_t)c * 1600 + t0 + tt];
    }
    __syncthreads();

    const int lane = tid & 31;
    const int w    = tid >> 5;
    const float NINF = __int_as_float(0xff800000u);

    float acc[4][13];
    #pragma unroll
    for (int r = 0; r < 4; r++)
        #pragma unroll
        for (int j = 0; j < 13; j++) acc[r][j] = 0.f;

    #pragma unroll 4
    for (int c = 0; c < 80; c++) {
        float kv[13];
        #pragma unroll
        for (int j = 0; j < 13; j++) {
            int s = lane + 32 * j;
            kv[j] = (s < 400) ? __bfloat162float(Ks[c * 408 + s]) : 0.f;
        }
        float qv[4];
        #pragma unroll
        for (int r = 0; r < 4; r++) qv[r] = Qs[c][w * 4 + r];
        #pragma unroll
        for (int r = 0; r < 4; r++)
            #pragma unroll
            for (int j = 0; j < 13; j++)
                acc[r][j] += qv[r] * kv[j];
    }

    float k2v[13];
    int   mskv[13];
    #pragma unroll
    for (int j = 0; j < 13; j++) {
        int s = lane + 32 * j;
        k2v[j] = (s < 400) ? k2s[b * 400 + s] : 0.f;
        mskv[j] = (s < 400) ? msk_in[b * 400 + s] : 1;
    }

    #pragma unroll
    for (int r = 0; r < 4; r++) {
        const int t   = t0 + w * 4 + r;
        const float q2v = q2s[b * 1600 + t];

        float x[13];
        float mx = NINF;
        #pragma unroll
        for (int j = 0; j < 13; j++) {
            int s = lane + 32 * j;
            x[j] = (s < 400) ? (-TEMP * (q2v + k2v[j] - 2.f * acc[r][j])) : NINF;
            mx = fmaxf(mx, x[j]);
        }
        #pragma unroll
        for (int o = 16; o > 0; o >>= 1) mx = fmaxf(mx, __shfl_xor_sync(0xffffffffu, mx, o));
        float se = 0.f;
        #pragma unroll
        for (int j = 0; j < 13; j++) se += expf(x[j] - mx);
        #pragma unroll
        for (int o = 16; o > 0; o >>= 1) se += __shfl_xor_sync(0xffffffffu, se, o);
        const float lse = logf(se) + mx;

        const float* pr  = prior    + ((size_t)b * 1600 + t) * 400;
        float* lp_out    = logp_out + ((size_t)b * 1600 + t) * 400;
        float* at_out    = attn_out + ((size_t)b * 1600 + t) * 400;

        float y[13];
        float mx2 = NINF;
        #pragma unroll
        for (int j = 0; j < 13; j++) {
            int s = lane + 32 * j;
            if (s < 400) {
                float lp = x[j] - lse + logf(pr[s] + 1e-8f);
                lp_out[s] = lp;
                y[j] = mskv[j] ? NINF : lp;
            } else {
                y[j] = NINF;
            }
            mx2 = fmaxf(mx2, y[j]);
        }
        #pragma unroll
        for (int o = 16; o > 0; o >>= 1) mx2 = fmaxf(mx2, __shfl_xor_sync(0xffffffffu, mx2, o));
        float s2 = 0.f;
        #pragma unroll
        for (int j = 0; j < 13; j++) {
            float e = expf(y[j] - mx2);
            y[j] = e;
            s2 += e;
        }
        #pragma unroll
        for (int o = 16; o > 0; o >>= 1) s2 += __shfl_xor_sync(0xffffffffu, s2, o);
        const float inv = 1.f / s2;
        #pragma unroll
        for (int j = 0; j < 13; j++) {
            int s = lane + 32 * j;
            if (s < 400) at_out[s] = y[j] * inv;
        }
    }
}

// ---------------- launch ----------------
extern "C" void kernel_launch(void* const* d_in, const int* in_sizes, int n_in,
                              void* d_out, int out_size)
{
    const float* queries = (const float*)d_in[0];
    const float* keys    = (const float*)d_in[1];
    const int*   mask    = (const int*)d_in[2];
    const float* prior   = (const float*)d_in[3];
    const float* se      = (const float*)d_in[4];
    const float* Wk1     = (const float*)d_in[5];
    const float* bk1     = (const float*)d_in[6];
    const float* Wk2     = (const float*)d_in[7];
    const float* bk2     = (const float*)d_in[8];
    const float* Wq1     = (const float*)d_in[9];
    const float* bq1     = (const float*)d_in[10];
    const float* Wq2     = (const float*)d_in[11];
    const float* bq2     = (const float*)d_in[12];
    const float* Wq3     = (const float*)d_in[13];
    const float* bq3     = (const float*)d_in[14];
    const float* Wks     = (const float*)d_in[15];
    const float* bks     = (const float*)d_in[16];
    const float* Wqs     = (const float*)d_in[17];
    const float* bqs     = (const float*)d_in[18];
    float* out = (float*)d_out;

    float *kb, *qb, *qf, *k2s, *q2s;
    bf16 *keys3, *que3, *pWk1, *pWk2, *pWq1, *pWq2, *pWq3, *k1b, *q1b, *q2b, *kfb;
    cudaGetSymbolAddress((void**)&kb,    g_kb);
    cudaGetSymbolAddress((void**)&qb,    g_qb);
    cudaGetSymbolAddress((void**)&keys3, g_keys3);
    cudaGetSymbolAddress((void**)&que3,  g_que3);
    cudaGetSymbolAddress((void**)&pWk1,  g_pWk1);
    cudaGetSymbolAddress((void**)&pWk2,  g_pWk2);
    cudaGetSymbolAddress((void**)&pWq1,  g_pWq1);
    cudaGetSymbolAddress((void**)&pWq2,  g_pWq2);
    cudaGetSymbolAddress((void**)&pWq3,  g_pWq3);
    cudaGetSymbolAddress((void**)&k1b,   g_k1b);
    cudaGetSymbolAddress((void**)&q1b,   g_q1b);
    cudaGetSymbolAddress((void**)&q2b,   g_q2b);
    cudaGetSymbolAddress((void**)&kfb,   g_kfb);
    cudaGetSymbolAddress((void**)&qf,    g_q);
    cudaGetSymbolAddress((void**)&k2s,   g_k2s);
    cudaGetSymbolAddress((void**)&q2s,   g_q2s);

    float* attn_out = out;
    float* logp_out = out + (size_t)B_ * T1_ * T2_;

    // speaker projections
    bias_proj_kernel<<<dim3(CTXT / 8, B_), 256>>>(se, Wks, bks, kb, CTXT, CTXT);
    bias_proj_kernel<<<dim3((CMEL + 7) / 8, B_), 256>>>(se, Wqs, bqs, qb, CTXT, CMEL);

    // weight packing
    pack_w3_kernel<<<(1024 * 512 * 3 + 255) / 256, 256>>>(Wk1, pWk1, 1024, 512);
    pack_w3_kernel<<<(160 * 80 * 3 + 255) / 256, 256>>>(Wq1, pWq1, 160, 80);
    pack_w1_kernel<<<(80 * 1024 + 255) / 256, 256>>>(Wk2, pWk2, 80 * 1024);
    pack_w1_kernel<<<(80 * 160 + 255) / 256, 256>>>(Wq2, pWq2, 80 * 160);
    pack_w1_kernel<<<(80 * 80 + 255) / 256, 256>>>(Wq3, pWq3, 80 * 80);

    // input prep (bias + 3 shifted copies, bf16)
    prep_x3_kernel<<<dim3((T2_ + 255) / 256, B_ * CTXT), 256>>>(keys, kb, keys3, CTXT, T2_);
    prep_x3_kernel<<<dim3((T1_ + 255) / 256, B_ * CMEL), 256>>>(queries, qb, que3, CMEL, T1_);

    // key path
    gemm_conv_kernel<3, true,  true ><<<dim3((T2_ + 127) / 128, 16, B_), 256>>>(pWk1, keys3, bk1, k1b, CTXT, 1024, 1536, T2_);
    gemm_conv_kernel<1, false, true ><<<dim3((T2_ + 127) / 128, 2,  B_), 256>>>(pWk2, k1b, bk2, kfb, 1024, 80, 1024, T2_);

    // query path
    gemm_conv_kernel<3, true,  true ><<<dim3((T1_ + 127) / 128, 3,  B_), 256>>>(pWq1, que3, bq1, q1b, CMEL, 160, 240, T1_);
    gemm_conv_kernel<1, true,  true ><<<dim3((T1_ + 127) / 128, 2,  B_), 256>>>(pWq2, q1b, bq2, q2b, 160, 80, 160, T1_);
    gemm_conv_kernel<1, false, false><<<dim3((T1_ + 127) / 128, 2,  B_), 256>>>(pWq3, q2b, bq3, qf, 80, 80, 80, T1_);

    // norms
    sumsq_bf16_kernel<<<dim3((T2_ + 255) / 256, B_), 256>>>(kfb, k2s, CATT, T2_);
    sumsq_kernel<<<dim3((T1_ + 255) / 256, B_), 256>>>(qf, q2s, CATT, T1_);

    // fused attention epilogue
    const int ks_bytes = 80 * 408 * sizeof(bf16);
    cudaFuncSetAttribute(attn_kernel, cudaFuncAttributeMaxDynamicSharedMemorySize, ks_bytes);
    attn_kernel<<<dim3(T1_ / 32, B_), 256, ks_bytes>>>(qf, kfb, q2s, k2s, prior, mask, attn_out, logp_out);
}

// round 7
// speedup vs baseline: 5.6003x; 1.2273x over previous
#include <cuda_runtime.h>
#include <cuda_bf16.h>
#include <cstdint>
#include <math.h>

#define TEMP 0.0005f
#define B_   32
#define CMEL 80
#define CTXT 512
#define CATT 80
#define T1_  1600
#define T2_  400

typedef __nv_bfloat16 bf16;

// ---------------- scratch (device globals; no allocation) ----------------
__device__ float g_kb [B_ * CTXT];
__device__ float g_qb [B_ * CMEL];
__device__ bf16  g_keys3[3u * B_ * CTXT * T2_];
__device__ bf16  g_que3 [3u * B_ * CMEL * T1_];
__device__ bf16  g_pWk1[1024 * 1536];
__device__ bf16  g_pWk2[80 * 1024];
__device__ bf16  g_pWq1[160 * 240];
__device__ bf16  g_pWq2[80 * 160];
__device__ bf16  g_pWq3[80 * 80];
__device__ bf16  g_k1b[(size_t)B_ * 1024 * T2_];
__device__ bf16  g_q1b[(size_t)B_ * 160 * T1_];
__device__ bf16  g_q2b[(size_t)B_ * 80 * T1_];
__device__ bf16  g_kfb[(size_t)B_ * CATT * T2_];
__device__ bf16  g_qfb[(size_t)B_ * CATT * T1_];
__device__ float g_k2s[B_ * T2_];
__device__ float g_q2s[B_ * T1_];

// ---------------- speaker projection ----------------
__global__ void bias_proj_kernel(const float* __restrict__ se, const float* __restrict__ W,
                                 const float* __restrict__ bias, float* __restrict__ out,
                                 int Cin, int Cout)
{
    int b    = blockIdx.y;
    int co   = blockIdx.x * 8 + (threadIdx.x >> 5);
    int lane = threadIdx.x & 31;
    if (co >= Cout) return;
    const float* s = se + (size_t)b * Cin;
    const float* w = W  + (size_t)co * Cin;
    float acc = 0.f;
    for (int i = lane; i < Cin; i += 32) acc += s[i] * w[i];
    #pragma unroll
    for (int o = 16; o > 0; o >>= 1) acc += __shfl_xor_sync(0xffffffffu, acc, o);
    if (lane == 0) out[b * Cout + co] = acc + bias[co];
}

// ---------------- prep: pack weights ----------------
__global__ void pack_w3_kernel(const float* __restrict__ W, bf16* __restrict__ out,
                               int Cout, int Cin)
{
    int i = blockIdx.x * 256 + threadIdx.x;
    int n = Cout * Cin * 3;
    if (i >= n) return;
    int co = i / (Cin * 3), r = i - co * Cin * 3;
    int ci = r / 3, d = r - ci * 3;
    out[(size_t)co * Cin * 3 + d * Cin + ci] = __float2bfloat16(W[i]);
}

__global__ void pack_w1_kernel(const float* __restrict__ W, bf16* __restrict__ out, int n)
{
    int i = blockIdx.x * 256 + threadIdx.x;
    if (i < n) out[i] = __float2bfloat16(W[i]);
}

// ---------------- prep: biased + shifted inputs (3 taps) ----------------
__global__ void prep_x3_kernel(const float* __restrict__ x, const float* __restrict__ chb,
                               bf16* __restrict__ out, int Cin, int T)
{
    int bc = blockIdx.y;
    int t  = blockIdx.x * 256 + threadIdx.x;
    if (t >= T) return;
    float  ca = chb[bc];
    float  v  = x[(size_t)bc * T + t] + ca;
    bf16   bv = __float2bfloat16(v);
    size_t plane = (size_t)B_ * Cin * T;
    size_t base  = (size_t)bc * T;
    out[plane + base + t] = bv;                           // d=1 (center)
    if (t + 1 < T) out[base + t + 1] = bv;                // d=0
    if (t == 0)     out[base + 0] = __float2bfloat16(0.f);
    if (t >= 1)     out[2 * plane + base + t - 1] = bv;   // d=2
    if (t == T - 1) out[2 * plane + base + T - 1] = __float2bfloat16(0.f);
}

// ---------------- MMA helpers ----------------
__device__ __forceinline__ uint32_t smem_u32(const void* p) {
    return (uint32_t)__cvta_generic_to_shared(p);
}
__device__ __forceinline__ void ldsm_x4(uint32_t* r, uint32_t addr) {
    asm volatile("ldmatrix.sync.aligned.m8n8.x4.shared.b16 {%0,%1,%2,%3}, [%4];"
                 : "=r"(r[0]), "=r"(r[1]), "=r"(r[2]), "=r"(r[3]) : "r"(addr));
}
__device__ __forceinline__ void ldsm_x4_t(uint32_t* r, uint32_t addr) {
    asm volatile("ldmatrix.sync.aligned.m8n8.x4.trans.shared.b16 {%0,%1,%2,%3}, [%4];"
                 : "=r"(r[0]), "=r"(r[1]), "=r"(r[2]), "=r"(r[3]) : "r"(addr));
}
__device__ __forceinline__ void mma_bf16(float* c, const uint32_t* a, const uint32_t* b) {
    asm volatile("mma.sync.aligned.m16n8k16.row.col.f32.bf16.bf16.f32 "
                 "{%0,%1,%2,%3}, {%4,%5,%6,%7}, {%8,%9}, {%0,%1,%2,%3};"
                 : "+f"(c[0]), "+f"(c[1]), "+f"(c[2]), "+f"(c[3])
                 : "r"(a[0]), "r"(a[1]), "r"(a[2]), "r"(a[3]), "r"(b[0]), "r"(b[1]));
}
__device__ __forceinline__ void cp16(void* sdst, const void* gsrc, int sz) {
    asm volatile("cp.async.cg.shared.global [%0], [%1], 16, %2;"
                 :: "r"(smem_u32(sdst)), "l"(gsrc), "r"(sz) : "memory");
}

// ---------------- bf16 GEMM (conv as GEMM) ----------------
template<int TAPS, bool RELU, bool OUT_BF16>
__global__ __launch_bounds__(256)
void gemm_conv_kernel(const bf16* __restrict__ A, const bf16* __restrict__ X,
                      const float* __restrict__ bias, void* __restrict__ Y,
                      int Cin, int Cout, int Ktot, int T)
{
    __shared__ __align__(16) bf16 As[2][64][40];
    __shared__ __align__(16) bf16 Bs[2][32][136];

    const int b   = blockIdx.z;
    const int co0 = blockIdx.y * 64;
    const int t0  = blockIdx.x * 128;
    const int tid = threadIdx.x;
    const int lane = tid & 31, wid = tid >> 5;
    const int wm = wid >> 2, wn = wid & 3;
    const int NC = (Ktot + 31) >> 5;

    const int a_row = tid >> 2;
    const int a_seg = (tid & 3) << 3;

    auto stage = [&](int c, int buf) {
        const int k0 = c << 5;
        {
            int kk = k0 + a_seg;
            const bf16* src = A;
            int sz = 0;
            if ((co0 + a_row) < Cout && kk < Ktot) {
                src = A + (size_t)(co0 + a_row) * Ktot + kk;
                sz = 16;
            }
            cp16(&As[buf][a_row][a_seg], src, sz);
        }
        #pragma unroll
        for (int i = 0; i < 2; i++) {
            int u = tid + (i << 8);
            int krow = u >> 4;
            int tseg = (u & 15) << 3;
            int k  = k0 + krow;
            int tg = t0 + tseg;
            const bf16* src = X;
            int sz = 0;
            if (k < Ktot && tg < T) {
                if (TAPS == 3) {
                    int d  = (k >= 2 * Cin) ? 2 : ((k >= Cin) ? 1 : 0);
                    int ci = k - d * Cin;
                    src = X + ((size_t)(d * B_ + b) * Cin + ci) * T + tg;
                } else {
                    src = X + ((size_t)b * Cin + k) * T + tg;
                }
                sz = 16;
            }
            cp16(&Bs[buf][krow][tseg], src, sz);
        }
        asm volatile("cp.async.commit_group;" ::: "memory");
    };

    float acc[2][4][4];
    #pragma unroll
    for (int m = 0; m < 2; m++)
        #pragma unroll
        for (int n = 0; n < 4; n++)
            #pragma unroll
            for (int r = 0; r < 4; r++) acc[m][n][r] = 0.f;

    const int lr = lane & 15, lh = lane >> 4;
    const uint32_t a_base = smem_u32(&As[0][wm * 32 + lr][lh * 8]);
    const uint32_t b_base = smem_u32(&Bs[0][lr][wn * 32 + lh * 8]);
    const uint32_t ABUF = 64 * 40 * 2;
    const uint32_t BBUF = 32 * 136 * 2;

    stage(0, 0);
    for (int c = 0; c < NC; c++) {
        const int buf = c & 1;
        if (c + 1 < NC) {
            stage(c + 1, buf ^ 1);
            asm volatile("cp.async.wait_group 1;" ::: "memory");
        } else {
            asm volatile("cp.async.wait_group 0;" ::: "memory");
        }
        __syncthreads();

        #pragma unroll
        for (int k16 = 0; k16 < 32; k16 += 16) {
            uint32_t aaddr = a_base + buf * ABUF + k16 * 2;
            uint32_t baddr = b_base + buf * BBUF + k16 * 272;
            uint32_t af0[4], af1[4], bf0[4], bf1[4];
            ldsm_x4(af0, aaddr);
            ldsm_x4(af1, aaddr + 16 * 80);
            ldsm_x4_t(bf0, baddr);
            ldsm_x4_t(bf1, baddr + 32);
            mma_bf16(acc[0][0], af0, bf0);
            mma_bf16(acc[0][1], af0, bf0 + 2);
            mma_bf16(acc[0][2], af0, bf1);
            mma_bf16(acc[0][3], af0, bf1 + 2);
            mma_bf16(acc[1][0], af1, bf0);
            mma_bf16(acc[1][1], af1, bf0 + 2);
            mma_bf16(acc[1][2], af1, bf1);
            mma_bf16(acc[1][3], af1, bf1 + 2);
        }
        __syncthreads();
    }

    const int g   = lane >> 2;
    const int c2  = (lane & 3) << 1;
    #pragma unroll
    for (int m = 0; m < 2; m++) {
        #pragma unroll
        for (int n = 0; n < 4; n++) {
            int row = co0 + wm * 32 + m * 16 + g;
            int col = t0 + wn * 32 + n * 8 + c2;
            #pragma unroll
            for (int h = 0; h < 2; h++) {
                int rr = row + h * 8;
                if (rr >= Cout || col >= T) continue;
                float bvs = bias[rr];
                float v0 = acc[m][n][h * 2 + 0] + bvs;
                float v1 = acc[m][n][h * 2 + 1] + bvs;
                if (RELU) { v0 = fmaxf(v0, 0.f); v1 = fmaxf(v1, 0.f); }
                if (OUT_BF16) {
                    bf16* yb = (bf16*)Y + ((size_t)b * Cout + rr) * T + col;
                    __nv_bfloat162 p = __floats2bfloat162_rn(v0, v1);
                    *(__nv_bfloat162*)yb = p;
                } else {
                    float* yb = (float*)Y + ((size_t)b * Cout + rr) * T + col;
                    yb[0] = v0; yb[1] = v1;
                }
            }
        }
    }
}

// ---------------- sum of squares (bf16 input) ----------------
__global__ void sumsq_bf16_kernel(const bf16* __restrict__ x, float* __restrict__ out, int C, int T)
{
    int b = blockIdx.y;
    int t = blockIdx.x * 256 + threadIdx.x;
    if (t >= T) return;
    const bf16* xb = x + (size_t)b * C * T;
    float s = 0.f;
    for (int c = 0; c < C; c++) {
        float v = __bfloat162float(xb[(size_t)c * T + t]);
        s += v * v;
    }
    out[b * T + t] = s;
}

// ---------------- attn: MMA qk + fused double softmax ----------------
// Block: 32 t-rows x 416 s-cols (400 valid). 256 threads.
// Phase 1: load K [80][408] bf16 + Q [80][40] bf16 to smem.
// Phase 2: warp w computes m16 tile (w&1), 13 n8-tiles at (w>>1)*104.
// Phase 3: scores -> smem fp32 [32][416] (overlays K region).
// Phase 4: per-warp row softmax; 2nd softmax via e1*prior renormalization (no 2nd exp).
#define KS_PITCH 408
#define SC_PITCH 416
#define ATTN_SMEM (80 * KS_PITCH * 2 + 80 * 40 * 2)

__global__ __launch_bounds__(256)
void attn_mma_kernel(const bf16* __restrict__ qfb, const bf16* __restrict__ kfb,
                     const float* __restrict__ q2s, const float* __restrict__ k2s,
                     const float* __restrict__ prior, const int* __restrict__ msk_in,
                     float* __restrict__ attn_out, float* __restrict__ logp_out)
{
    extern __shared__ __align__(16) char sm_[];
    bf16*  Ks = (bf16*)sm_;                           // [80][408]
    bf16*  Qs = (bf16*)(sm_ + 80 * KS_PITCH * 2);     // [80][40]
    float* Sc = (float*)sm_;                          // [32][416] overlay

    const int b   = blockIdx.y;
    const int t0  = blockIdx.x * 32;
    const int tid = threadIdx.x;
    const int lane = tid & 31, w = tid >> 5;
    const float NINF = __int_as_float(0xff800000u);

    // load K tile + zero pad
    const bf16* kbp = kfb + (size_t)b * 80 * 400;
    for (int i = tid; i < 80 * 50; i += 256) {
        int c = i / 50, s8 = (i - c * 50) * 8;
        *(uint4*)&Ks[c * KS_PITCH + s8] = *(const uint4*)&kbp[c * 400 + s8];
    }
    if (tid < 80) *(uint4*)&Ks[tid * KS_PITCH + 400] = make_uint4(0, 0, 0, 0);
    // load Q tile
    const bf16* qbp = qfb + (size_t)b * 80 * 1600 + t0;
    for (int i = tid; i < 80 * 4; i += 256) {
        int c = i >> 2, s8 = (i & 3) * 8;
        *(uint4*)&Qs[c * 40 + s8] = *(const uint4*)&qbp[(size_t)c * 1600 + s8];
    }
    __syncthreads();

    // MMA: qk
    const int m0    = (w & 1) * 16;
    const int nbase = (w >> 1) * 104;
    float acc[13][4];
    #pragma unroll
    for (int j = 0; j < 13; j++)
        #pragma unroll
        for (int r = 0; r < 4; r++) acc[j][r] = 0.f;

    const int lr2 = lane & 7, selA = (lane >> 3) & 1, khA = lane >> 4;
    const int lrB = lane & 15, lhB = lane >> 4;

    #pragma unroll
    for (int ks = 0; ks < 5; ks++) {
        uint32_t af[4];
        ldsm_x4_t(af, smem_u32(Qs + (ks * 16 + khA * 8 + lr2) * 40 + m0 + selA * 8));
        #pragma unroll
        for (int jj = 0; jj < 7; jj++) {
            uint32_t bfr[4];
            ldsm_x4_t(bfr, smem_u32(Ks + (ks * 16 + lrB) * KS_PITCH + nbase + jj * 16 + lhB * 8));
            mma_bf16(acc[2 * jj], af, bfr);
            if (2 * jj + 1 < 13) mma_bf16(acc[2 * jj + 1], af, bfr + 2);
        }
    }
    __syncthreads();   // all Ks reads done before Sc overlays

    // scores to smem
    const int g  = lane >> 2;
    const int c2 = (lane & 3) << 1;
    #pragma unroll
    for (int j = 0; j < 13; j++) {
        int col = nbase + j * 8 + c2;
        *(float2*)&Sc[(m0 + g) * SC_PITCH + col]     = make_float2(acc[j][0], acc[j][1]);
        *(float2*)&Sc[(m0 + 8 + g) * SC_PITCH + col] = make_float2(acc[j][2], acc[j][3]);
    }
    __syncthreads();

    // per-warp row softmax: warp w owns rows 4w..4w+3
    float k2v[13];
    int   mv[13];
    #pragma unroll
    for (int j = 0; j < 13; j++) {
        int s = lane + 32 * j;
        k2v[j] = (s < 400) ? k2s[b * 400 + s] : 0.f;
        mv[j]  = (s < 400) ? msk_in[b * 400 + s] : 1;
    }

    #pragma unroll
    for (int rr = 0; rr < 4; rr++) {
        const int trow = 4 * w + rr;
        const int t    = t0 + trow;
        const float q2v = q2s[b * 1600 + t];

        float x[13], e[13];
        float mx = NINF;
        #pragma unroll
        for (int j = 0; j < 13; j++) {
            int s = lane + 32 * j;
            float qk = Sc[trow * SC_PITCH + s];
            x[j] = (s < 400) ? (-TEMP * (q2v + k2v[j] - 2.f * qk)) : NINF;
            mx = fmaxf(mx, x[j]);
        }
        #pragma unroll
        for (int o = 16; o > 0; o >>= 1) mx = fmaxf(mx, __shfl_xor_sync(0xffffffffu, mx, o));

        float se = 0.f;
        #pragma unroll
        for (int j = 0; j < 13; j++) {
            e[j] = __expf(x[j] - mx);           // exp(-inf)=0 for pads
            se += e[j];
        }
        #pragma unroll
        for (int o = 16; o > 0; o >>= 1) se += __shfl_xor_sync(0xffffffffu, se, o);
        const float lse_m = __logf(se);         // lse - mx

        const float* pr = prior    + ((size_t)b * 1600 + t) * 400;
        float* lp_out   = logp_out + ((size_t)b * 1600 + t) * 400;
        float* at_out   = attn_out + ((size_t)b * 1600 + t) * 400;

        float s2 = 0.f;
        #pragma unroll
        for (int j = 0; j < 13; j++) {
            int s = lane + 32 * j;
            if (s < 400) {
                float pv = pr[s] + 1e-8f;
                float lp = x[j] - mx - lse_m + __logf(pv);
                lp_out[s] = lp;
                e[j] = mv[j] ? 0.f : e[j] * pv; // masked softmax weights (exp-free)
            } else {
                e[j] = 0.f;
            }
            s2 += e[j];
        }
        #pragma unroll
        for (int o = 16; o > 0; o >>= 1) s2 += __shfl_xor_sync(0xffffffffu, s2, o);
        const float inv = 1.f / s2;
        #pragma unroll
        for (int j = 0; j < 13; j++) {
            int s = lane + 32 * j;
            if (s < 400) at_out[s] = e[j] * inv;
        }
    }
}

// ---------------- launch ----------------
extern "C" void kernel_launch(void* const* d_in, const int* in_sizes, int n_in,
                              void* d_out, int out_size)
{
    const float* queries = (const float*)d_in[0];
    const float* keys    = (const float*)d_in[1];
    const int*   mask    = (const int*)d_in[2];
    const float* prior   = (const float*)d_in[3];
    const float* se      = (const float*)d_in[4];
    const float* Wk1     = (const float*)d_in[5];
    const float* bk1     = (const float*)d_in[6];
    const float* Wk2     = (const float*)d_in[7];
    const float* bk2     = (const float*)d_in[8];
    const float* Wq1     = (const float*)d_in[9];
    const float* bq1     = (const float*)d_in[10];
    const float* Wq2     = (const float*)d_in[11];
    const float* bq2     = (const float*)d_in[12];
    const float* Wq3     = (const float*)d_in[13];
    const float* bq3     = (const float*)d_in[14];
    const float* Wks     = (const float*)d_in[15];
    const float* bks     = (const float*)d_in[16];
    const float* Wqs     = (const float*)d_in[17];
    const float* bqs     = (const float*)d_in[18];
    float* out = (float*)d_out;

    float *kb, *qb, *k2s, *q2s;
    bf16 *keys3, *que3, *pWk1, *pWk2, *pWq1, *pWq2, *pWq3, *k1b, *q1b, *q2b, *kfb, *qfb;
    cudaGetSymbolAddress((void**)&kb,    g_kb);
    cudaGetSymbolAddress((void**)&qb,    g_qb);
    cudaGetSymbolAddress((void**)&keys3, g_keys3);
    cudaGetSymbolAddress((void**)&que3,  g_que3);
    cudaGetSymbolAddress((void**)&pWk1,  g_pWk1);
    cudaGetSymbolAddress((void**)&pWk2,  g_pWk2);
    cudaGetSymbolAddress((void**)&pWq1,  g_pWq1);
    cudaGetSymbolAddress((void**)&pWq2,  g_pWq2);
    cudaGetSymbolAddress((void**)&pWq3,  g_pWq3);
    cudaGetSymbolAddress((void**)&k1b,   g_k1b);
    cudaGetSymbolAddress((void**)&q1b,   g_q1b);
    cudaGetSymbolAddress((void**)&q2b,   g_q2b);
    cudaGetSymbolAddress((void**)&kfb,   g_kfb);
    cudaGetSymbolAddress((void**)&qfb,   g_qfb);
    cudaGetSymbolAddress((void**)&k2s,   g_k2s);
    cudaGetSymbolAddress((void**)&q2s,   g_q2s);

    float* attn_out = out;
    float* logp_out = out + (size_t)B_ * T1_ * T2_;

    // speaker projections
    bias_proj_kernel<<<dim3(CTXT / 8, B_), 256>>>(se, Wks, bks, kb, CTXT, CTXT);
    bias_proj_kernel<<<dim3((CMEL + 7) / 8, B_), 256>>>(se, Wqs, bqs, qb, CTXT, CMEL);

    // weight packing
    pack_w3_kernel<<<(1024 * 512 * 3 + 255) / 256, 256>>>(Wk1, pWk1, 1024, 512);
    pack_w3_kernel<<<(160 * 80 * 3 + 255) / 256, 256>>>(Wq1, pWq1, 160, 80);
    pack_w1_kernel<<<(80 * 1024 + 255) / 256, 256>>>(Wk2, pWk2, 80 * 1024);
    pack_w1_kernel<<<(80 * 160 + 255) / 256, 256>>>(Wq2, pWq2, 80 * 160);
    pack_w1_kernel<<<(80 * 80 + 255) / 256, 256>>>(Wq3, pWq3, 80 * 80);

    // input prep
    prep_x3_kernel<<<dim3((T2_ + 255) / 256, B_ * CTXT), 256>>>(keys, kb, keys3, CTXT, T2_);
    prep_x3_kernel<<<dim3((T1_ + 255) / 256, B_ * CMEL), 256>>>(queries, qb, que3, CMEL, T1_);

    // key path
    gemm_conv_kernel<3, true,  true ><<<dim3((T2_ + 127) / 128, 16, B_), 256>>>(pWk1, keys3, bk1, k1b, CTXT, 1024, 1536, T2_);
    gemm_conv_kernel<1, false, true ><<<dim3((T2_ + 127) / 128, 2,  B_), 256>>>(pWk2, k1b, bk2, kfb, 1024, 80, 1024, T2_);

    // query path
    gemm_conv_kernel<3, true,  true ><<<dim3((T1_ + 127) / 128, 3,  B_), 256>>>(pWq1, que3, bq1, q1b, CMEL, 160, 240, T1_);
    gemm_conv_kernel<1, true,  true ><<<dim3((T1_ + 127) / 128, 2,  B_), 256>>>(pWq2, q1b, bq2, q2b, 160, 80, 160, T1_);
    gemm_conv_kernel<1, false, true ><<<dim3((T1_ + 127) / 128, 2,  B_), 256>>>(pWq3, q2b, bq3, qfb, 80, 80, 80, T1_);

    // norms (from bf16 tensors — consistent with bf16 qk)
    sumsq_bf16_kernel<<<dim3((T2_ + 255) / 256, B_), 256>>>(kfb, k2s, CATT, T2_);
    sumsq_bf16_kernel<<<dim3((T1_ + 255) / 256, B_), 256>>>(qfb, q2s, CATT, T1_);

    // fused attention epilogue (tensor-core qk)
    cudaFuncSetAttribute(attn_mma_kernel, cudaFuncAttributeMaxDynamicSharedMemorySize, ATTN_SMEM);
    attn_mma_kernel<<<dim3(T1_ / 32, B_), 256, ATTN_SMEM>>>(qfb, kfb, q2s, k2s, prior, mask, attn_out, logp_out);
}

// round 13
// speedup vs baseline: 6.1805x; 1.1036x over previous
#include <cuda_runtime.h>
#include <cuda_bf16.h>
#include <cstdint>
#include <math.h>

#define TEMP 0.0005f
#define B_   32
#define CMEL 80
#define CTXT 512
#define CATT 80
#define T1_  1600
#define T2_  400

typedef __nv_bfloat16 bf16;

// ---------------- scratch (device globals; no allocation) ----------------
__device__ float g_kb [B_ * CTXT];
__device__ float g_qb [B_ * CMEL];
__device__ bf16  g_keys3[3u * B_ * CTXT * T2_];
__device__ bf16  g_que3 [3u * B_ * CMEL * T1_];
__device__ bf16  g_pWk1[1024 * 1536];
__device__ bf16  g_pWk2[80 * 1024];
__device__ bf16  g_pWq1[160 * 240];
__device__ bf16  g_pWq2[80 * 160];
__device__ bf16  g_pWq3[80 * 80];
__device__ bf16  g_k1b[(size_t)B_ * 1024 * T2_];
__device__ bf16  g_q1b[(size_t)B_ * 160 * T1_];
__device__ bf16  g_q2b[(size_t)B_ * 80 * T1_];
__device__ bf16  g_kfb[(size_t)B_ * CATT * T2_];
__device__ bf16  g_qfb[(size_t)B_ * CATT * T1_];
__device__ float g_k2s[B_ * T2_];
__device__ float g_q2s[B_ * T1_];

// ---------------- speaker projection ----------------
__global__ void bias_proj_kernel(const float* __restrict__ se, const float* __restrict__ W,
                                 const float* __restrict__ bias, float* __restrict__ out,
                                 int Cin, int Cout)
{
    int b    = blockIdx.y;
    int co   = blockIdx.x * 8 + (threadIdx.x >> 5);
    int lane = threadIdx.x & 31;
    if (co >= Cout) return;
    const float* s = se + (size_t)b * Cin;
    const float* w = W  + (size_t)co * Cin;
    float acc = 0.f;
    for (int i = lane; i < Cin; i += 32) acc += s[i] * w[i];
    #pragma unroll
    for (int o = 16; o > 0; o >>= 1) acc += __shfl_xor_sync(0xffffffffu, acc, o);
    if (lane == 0) out[b * Cout + co] = acc + bias[co];
}

// ---------------- prep: pack weights ----------------
__global__ void pack_w3_kernel(const float* __restrict__ W, bf16* __restrict__ out,
                               int Cout, int Cin)
{
    int i = blockIdx.x * 256 + threadIdx.x;
    int n = Cout * Cin * 3;
    if (i >= n) return;
    int co = i / (Cin * 3), r = i - co * Cin * 3;
    int ci = r / 3, d = r - ci * 3;
    out[(size_t)co * Cin * 3 + d * Cin + ci] = __float2bfloat16(W[i]);
}

__global__ void pack_w1_kernel(const float* __restrict__ W, bf16* __restrict__ out, int n)
{
    int i = blockIdx.x * 256 + threadIdx.x;
    if (i < n) out[i] = __float2bfloat16(W[i]);
}

// ---------------- prep: biased + shifted inputs (3 taps) ----------------
__global__ void prep_x3_kernel(const float* __restrict__ x, const float* __restrict__ chb,
                               bf16* __restrict__ out, int Cin, int T)
{
    int bc = blockIdx.y;
    int t  = blockIdx.x * 256 + threadIdx.x;
    if (t >= T) return;
    float  ca = chb[bc];
    float  v  = x[(size_t)bc * T + t] + ca;
    bf16   bv = __float2bfloat16(v);
    size_t plane = (size_t)B_ * Cin * T;
    size_t base  = (size_t)bc * T;
    out[plane + base + t] = bv;                           // d=1 (center)
    if (t + 1 < T) out[base + t + 1] = bv;                // d=0
    if (t == 0)     out[base + 0] = __float2bfloat16(0.f);
    if (t >= 1)     out[2 * plane + base + t - 1] = bv;   // d=2
    if (t == T - 1) out[2 * plane + base + T - 1] = __float2bfloat16(0.f);
}

// ---------------- MMA helpers ----------------
__device__ __forceinline__ uint32_t smem_u32(const void* p) {
    return (uint32_t)__cvta_generic_to_shared(p);
}
__device__ __forceinline__ void ldsm_x4(uint32_t* r, uint32_t addr) {
    asm volatile("ldmatrix.sync.aligned.m8n8.x4.shared.b16 {%0,%1,%2,%3}, [%4];"
                 : "=r"(r[0]), "=r"(r[1]), "=r"(r[2]), "=r"(r[3]) : "r"(addr));
}
__device__ __forceinline__ void ldsm_x4_t(uint32_t* r, uint32_t addr) {
    asm volatile("ldmatrix.sync.aligned.m8n8.x4.trans.shared.b16 {%0,%1,%2,%3}, [%4];"
                 : "=r"(r[0]), "=r"(r[1]), "=r"(r[2]), "=r"(r[3]) : "r"(addr));
}
__device__ __forceinline__ void mma_bf16(float* c, const uint32_t* a, const uint32_t* b) {
    asm volatile("mma.sync.aligned.m16n8k16.row.col.f32.bf16.bf16.f32 "
                 "{%0,%1,%2,%3}, {%4,%5,%6,%7}, {%8,%9}, {%0,%1,%2,%3};"
                 : "+f"(c[0]), "+f"(c[1]), "+f"(c[2]), "+f"(c[3])
                 : "r"(a[0]), "r"(a[1]), "r"(a[2]), "r"(a[3]), "r"(b[0]), "r"(b[1]));
}
__device__ __forceinline__ void cp16(void* sdst, const void* gsrc, int sz) {
    asm volatile("cp.async.cg.shared.global [%0], [%1], 16, %2;"
                 :: "r"(smem_u32(sdst)), "l"(gsrc), "r"(sz) : "memory");
}

// ---------------- bf16 GEMM 128x128, K-chunk 64, 2-stage cp.async ----------------
// A: [Cout][Ktot] bf16.  X: TAPS==1 -> [B][Ktot][T]; TAPS==3 -> [3][B][Cin][T].
// 8 warps = 4(m) x 2(n); warp tile 32co x 64t; acc[2][8][4] per thread.
#define A_PITCH 72
#define B_PITCH 136
#define ABUF (128 * A_PITCH * 2)
#define BBUF (64 * B_PITCH * 2)
#define G_SMEM (2 * ABUF + 2 * BBUF)     // 71680 B

template<int TAPS, bool RELU>
__global__ __launch_bounds__(256)
void gemm128_kernel(const bf16* __restrict__ A, const bf16* __restrict__ X,
                    const float* __restrict__ bias, bf16* __restrict__ Y,
                    int Cin, int Cout, int Ktot, int T)
{
    extern __shared__ __align__(16) char sm_[];
    bf16* As = (bf16*)sm_;                    // [2][128][72]
    bf16* Bs = (bf16*)(sm_ + 2 * ABUF);       // [2][64][136]

    const int b   = blockIdx.z;
    const int co0 = blockIdx.y * 128;
    const int t0  = blockIdx.x * 128;
    const int tid = threadIdx.x;
    const int lane = tid & 31, wid = tid >> 5;
    const int wm = wid >> 1, wn = wid & 1;
    const int NC = (Ktot + 63) >> 6;

    auto stage = [&](int c, int buf) {
        const int k0 = c << 6;
        bf16* Ab = As + buf * (128 * A_PITCH);
        bf16* Bb = Bs + buf * (64 * B_PITCH);
        #pragma unroll
        for (int i = 0; i < 4; i++) {        // A: 128 rows x 64 k = 1024 segs
            int u    = tid + (i << 8);
            int row  = u >> 3;
            int segc = (u & 7) << 3;
            int kk   = k0 + segc;
            const bf16* src = A;
            int sz = 0;
            if ((co0 + row) < Cout && kk < Ktot) {
                src = A + (size_t)(co0 + row) * Ktot + kk;
                sz = 16;
            }
            cp16(Ab + row * A_PITCH + segc, src, sz);
        }
        #pragma unroll
        for (int i = 0; i < 4; i++) {        // B: 64 k-rows x 128 t = 1024 segs
            int u    = tid + (i << 8);
            int krow = u >> 4;
            int tseg = (u & 15) << 3;
            int k    = k0 + krow;
            int tg   = t0 + tseg;
            const bf16* src = X;
            int sz = 0;
            if (k < Ktot && tg < T) {
                if (TAPS == 3) {
                    int d  = (k >= 2 * Cin) ? 2 : ((k >= Cin) ? 1 : 0);
                    int ci = k - d * Cin;
                    src = X + ((size_t)(d * B_ + b) * Cin + ci) * T + tg;
                } else {
                    src = X + ((size_t)b * Cin + k) * T + tg;
                }
                sz = 16;
            }
            cp16(Bb + krow * B_PITCH + tseg, src, sz);
        }
        asm volatile("cp.async.commit_group;" ::: "memory");
    };

    float acc[2][8][4];
    #pragma unroll
    for (int m = 0; m < 2; m++)
        #pragma unroll
        for (int n = 0; n < 8; n++)
            #pragma unroll
            for (int r = 0; r < 4; r++) acc[m][n][r] = 0.f;

    const int lr = lane & 15, lh = lane >> 4;
    const uint32_t a_base = smem_u32(As + (wm * 32 + lr) * A_PITCH + lh * 8);
    const uint32_t b_base = smem_u32(Bs + lr * B_PITCH + wn * 64 + lh * 8);

    stage(0, 0);
    for (int c = 0; c < NC; c++) {
        const int buf = c & 1;
        if (c + 1 < NC) {
            stage(c + 1, buf ^ 1);
            asm volatile("cp.async.wait_group 1;" ::: "memory");
        } else {
            asm volatile("cp.async.wait_group 0;" ::: "memory");
        }
        __syncthreads();

        #pragma unroll
        for (int ks = 0; ks < 64; ks += 16) {
            uint32_t af[2][4];
            ldsm_x4(af[0], a_base + buf * ABUF + ks * 2);
            ldsm_x4(af[1], a_base + buf * ABUF + 16 * A_PITCH * 2 + ks * 2);
            uint32_t bfr[4][4];
            #pragma unroll
            for (int j = 0; j < 4; j++)
                ldsm_x4_t(bfr[j], b_base + buf * BBUF + ks * (B_PITCH * 2) + j * 32);
            #pragma unroll
            for (int m = 0; m < 2; m++)
                #pragma unroll
                for (int j = 0; j < 4; j++) {
                    mma_bf16(acc[m][2 * j],     af[m], bfr[j]);
                    mma_bf16(acc[m][2 * j + 1], af[m], bfr[j] + 2);
                }
        }
        __syncthreads();
    }

    // epilogue (bf16 out)
    const int g  = lane >> 2;
    const int c2 = (lane & 3) << 1;
    #pragma unroll
    for (int m = 0; m < 2; m++) {
        #pragma unroll
        for (int n = 0; n < 8; n++) {
            int col = t0 + wn * 64 + n * 8 + c2;
            if (col >= T) continue;
            #pragma unroll
            for (int h = 0; h < 2; h++) {
                int rr = co0 + wm * 32 + m * 16 + h * 8 + g;
                if (rr >= Cout) continue;
                float bvs = bias[rr];
                float v0 = acc[m][n][h * 2 + 0] + bvs;
                float v1 = acc[m][n][h * 2 + 1] + bvs;
                if (RELU) { v0 = fmaxf(v0, 0.f); v1 = fmaxf(v1, 0.f); }
                __nv_bfloat162 p = __floats2bfloat162_rn(v0, v1);
                *(__nv_bfloat162*)(Y + ((size_t)b * Cout + rr) * T + col) = p;
            }
        }
    }
}

// ---------------- sum of squares (bf16 input) ----------------
__global__ void sumsq_bf16_kernel(const bf16* __restrict__ x, float* __restrict__ out, int C, int T)
{
    int b = blockIdx.y;
    int t = blockIdx.x * 256 + threadIdx.x;
    if (t >= T) return;
    const bf16* xb = x + (size_t)b * C * T;
    float s = 0.f;
    for (int c = 0; c < C; c++) {
        float v = __bfloat162float(xb[(size_t)c * T + t]);
        s += v * v;
    }
    out[b * T + t] = s;
}

// ---------------- attn: MMA qk + fused double softmax ----------------
#define KS_PITCH 408
#define SC_PITCH 416
#define ATTN_SMEM (80 * KS_PITCH * 2 + 80 * 40 * 2)

__global__ __launch_bounds__(256)
void attn_mma_kernel(const bf16* __restrict__ qfb, const bf16* __restrict__ kfb,
                     const float* __restrict__ q2s, const float* __restrict__ k2s,
                     const float* __restrict__ prior, const int* __restrict__ msk_in,
                     float* __restrict__ attn_out, float* __restrict__ logp_out)
{
    extern __shared__ __align__(16) char sm_[];
    bf16*  Ks = (bf16*)sm_;                           // [80][408]
    bf16*  Qs = (bf16*)(sm_ + 80 * KS_PITCH * 2);     // [80][40]
    float* Sc = (float*)sm_;                          // [32][416] overlay

    const int b   = blockIdx.y;
    const int t0  = blockIdx.x * 32;
    const int tid = threadIdx.x;
    const int lane = tid & 31, w = tid >> 5;
    const float NINF = __int_as_float(0xff800000u);

    const bf16* kbp = kfb + (size_t)b * 80 * 400;
    for (int i = tid; i < 80 * 50; i += 256) {
        int c = i / 50, s8 = (i - c * 50) * 8;
        *(uint4*)&Ks[c * KS_PITCH + s8] = *(const uint4*)&kbp[c * 400 + s8];
    }
    if (tid < 80) *(uint4*)&Ks[tid * KS_PITCH + 400] = make_uint4(0, 0, 0, 0);
    const bf16* qbp = qfb + (size_t)b * 80 * 1600 + t0;
    for (int i = tid; i < 80 * 4; i += 256) {
        int c = i >> 2, s8 = (i & 3) * 8;
        *(uint4*)&Qs[c * 40 + s8] = *(const uint4*)&qbp[(size_t)c * 1600 + s8];
    }
    __syncthreads();

    const int m0    = (w & 1) * 16;
    const int nbase = (w >> 1) * 104;
    float acc[13][4];
    #pragma unroll
    for (int j = 0; j < 13; j++)
        #pragma unroll
        for (int r = 0; r < 4; r++) acc[j][r] = 0.f;

    const int lr2 = lane & 7, selA = (lane >> 3) & 1, khA = lane >> 4;
    const int lrB = lane & 15, lhB = lane >> 4;

    #pragma unroll
    for (int ks = 0; ks < 5; ks++) {
        uint32_t af[4];
        ldsm_x4_t(af, smem_u32(Qs + (ks * 16 + khA * 8 + lr2) * 40 + m0 + selA * 8));
        #pragma unroll
        for (int jj = 0; jj < 7; jj++) {
            uint32_t bfr[4];
            ldsm_x4_t(bfr, smem_u32(Ks + (ks * 16 + lrB) * KS_PITCH + nbase + jj * 16 + lhB * 8));
            mma_bf16(acc[2 * jj], af, bfr);
            if (2 * jj + 1 < 13) mma_bf16(acc[2 * jj + 1], af, bfr + 2);
        }
    }
    __syncthreads();

    const int g  = lane >> 2;
    const int c2 = (lane & 3) << 1;
    #pragma unroll
    for (int j = 0; j < 13; j++) {
        int col = nbase + j * 8 + c2;
        *(float2*)&Sc[(m0 + g) * SC_PITCH + col]     = make_float2(acc[j][0], acc[j][1]);
        *(float2*)&Sc[(m0 + 8 + g) * SC_PITCH + col] = make_float2(acc[j][2], acc[j][3]);
    }
    __syncthreads();

    float k2v[13];
    int   mv[13];
    #pragma unroll
    for (int j = 0; j < 13; j++) {
        int s = lane + 32 * j;
        k2v[j] = (s < 400) ? k2s[b * 400 + s] : 0.f;
        mv[j]  = (s < 400) ? msk_in[b * 400 + s] : 1;
    }

    #pragma unroll
    for (int rr = 0; rr < 4; rr++) {
        const int trow = 4 * w + rr;
        const int t    = t0 + trow;
        const float q2v = q2s[b * 1600 + t];

        float x[13], e[13];
        float mx = NINF;
        #pragma unroll
        for (int j = 0; j < 13; j++) {
            int s = lane + 32 * j;
            float qk = Sc[trow * SC_PITCH + s];
            x[j] = (s < 400) ? (-TEMP * (q2v + k2v[j] - 2.f * qk)) : NINF;
            mx = fmaxf(mx, x[j]);
        }
        #pragma unroll
        for (int o = 16; o > 0; o >>= 1) mx = fmaxf(mx, __shfl_xor_sync(0xffffffffu, mx, o));

        float se = 0.f;
        #pragma unroll
        for (int j = 0; j < 13; j++) {
            e[j] = __expf(x[j] - mx);
            se += e[j];
        }
        #pragma unroll
        for (int o = 16; o > 0; o >>= 1) se += __shfl_xor_sync(0xffffffffu, se, o);
        const float lse_m = __logf(se);

        const float* pr = prior    + ((size_t)b * 1600 + t) * 400;
        float* lp_out   = logp_out + ((size_t)b * 1600 + t) * 400;
        float* at_out   = attn_out + ((size_t)b * 1600 + t) * 400;

        float s2 = 0.f;
        #pragma unroll
        for (int j = 0; j < 13; j++) {
            int s = lane + 32 * j;
            if (s < 400) {
                float pv = pr[s] + 1e-8f;
                float lp = x[j] - mx - lse_m + __logf(pv);
                lp_out[s] = lp;
                e[j] = mv[j] ? 0.f : e[j] * pv;
            } else {
                e[j] = 0.f;
            }
            s2 += e[j];
        }
        #pragma unroll
        for (int o = 16; o > 0; o >>= 1) s2 += __shfl_xor_sync(0xffffffffu, s2, o);
        const float inv = 1.f / s2;
        #pragma unroll
        for (int j = 0; j < 13; j++) {
            int s = lane + 32 * j;
            if (s < 400) at_out[s] = e[j] * inv;
        }
    }
}

// ---------------- launch ----------------
extern "C" void kernel_launch(void* const* d_in, const int* in_sizes, int n_in,
                              void* d_out, int out_size)
{
    const float* queries = (const float*)d_in[0];
    const float* keys    = (const float*)d_in[1];
    const int*   mask    = (const int*)d_in[2];
    const float* prior   = (const float*)d_in[3];
    const float* se      = (const float*)d_in[4];
    const float* Wk1     = (const float*)d_in[5];
    const float* bk1     = (const float*)d_in[6];
    const float* Wk2     = (const float*)d_in[7];
    const float* bk2     = (const float*)d_in[8];
    const float* Wq1     = (const float*)d_in[9];
    const float* bq1     = (const float*)d_in[10];
    const float* Wq2     = (const float*)d_in[11];
    const float* bq2     = (const float*)d_in[12];
    const float* Wq3     = (const float*)d_in[13];
    const float* bq3     = (const float*)d_in[14];
    const float* Wks     = (const float*)d_in[15];
    const float* bks     = (const float*)d_in[16];
    const float* Wqs     = (const float*)d_in[17];
    const float* bqs     = (const float*)d_in[18];
    float* out = (float*)d_out;

    float *kb, *qb, *k2s, *q2s;
    bf16 *keys3, *que3, *pWk1, *pWk2, *pWq1, *pWq2, *pWq3, *k1b, *q1b, *q2b, *kfb, *qfb;
    cudaGetSymbolAddress((void**)&kb,    g_kb);
    cudaGetSymbolAddress((void**)&qb,    g_qb);
    cudaGetSymbolAddress((void**)&keys3, g_keys3);
    cudaGetSymbolAddress((void**)&que3,  g_que3);
    cudaGetSymbolAddress((void**)&pWk1,  g_pWk1);
    cudaGetSymbolAddress((void**)&pWk2,  g_pWk2);
    cudaGetSymbolAddress((void**)&pWq1,  g_pWq1);
    cudaGetSymbolAddress((void**)&pWq2,  g_pWq2);
    cudaGetSymbolAddress((void**)&pWq3,  g_pWq3);
    cudaGetSymbolAddress((void**)&k1b,   g_k1b);
    cudaGetSymbolAddress((void**)&q1b,   g_q1b);
    cudaGetSymbolAddress((void**)&q2b,   g_q2b);
    cudaGetSymbolAddress((void**)&kfb,   g_kfb);
    cudaGetSymbolAddress((void**)&qfb,   g_qfb);
    cudaGetSymbolAddress((void**)&k2s,   g_k2s);
    cudaGetSymbolAddress((void**)&q2s,   g_q2s);

    float* attn_out = out;
    float* logp_out = out + (size_t)B_ * T1_ * T2_;

    // one-time attribute setup (idempotent, graph-safe)
    cudaFuncSetAttribute(gemm128_kernel<3, true>,  cudaFuncAttributeMaxDynamicSharedMemorySize, G_SMEM);
    cudaFuncSetAttribute(gemm128_kernel<1, true>,  cudaFuncAttributeMaxDynamicSharedMemorySize, G_SMEM);
    cudaFuncSetAttribute(gemm128_kernel<1, false>, cudaFuncAttributeMaxDynamicSharedMemorySize, G_SMEM);
    cudaFuncSetAttribute(attn_mma_kernel, cudaFuncAttributeMaxDynamicSharedMemorySize, ATTN_SMEM);

    // speaker projections
    bias_proj_kernel<<<dim3(CTXT / 8, B_), 256>>>(se, Wks, bks, kb, CTXT, CTXT);
    bias_proj_kernel<<<dim3((CMEL + 7) / 8, B_), 256>>>(se, Wqs, bqs, qb, CTXT, CMEL);

    // weight packing
    pack_w3_kernel<<<(1024 * 512 * 3 + 255) / 256, 256>>>(Wk1, pWk1, 1024, 512);
    pack_w3_kernel<<<(160 * 80 * 3 + 255) / 256, 256>>>(Wq1, pWq1, 160, 80);
    pack_w1_kernel<<<(80 * 1024 + 255) / 256, 256>>>(Wk2, pWk2, 80 * 1024);
    pack_w1_kernel<<<(80 * 160 + 255) / 256, 256>>>(Wq2, pWq2, 80 * 160);
    pack_w1_kernel<<<(80 * 80 + 255) / 256, 256>>>(Wq3, pWq3, 80 * 80);

    // input prep
    prep_x3_kernel<<<dim3((T2_ + 255) / 256, B_ * CTXT), 256>>>(keys, kb, keys3, CTXT, T2_);
    prep_x3_kernel<<<dim3((T1_ + 255) / 256, B_ * CMEL), 256>>>(queries, qb, que3, CMEL, T1_);

    // key path
    gemm128_kernel<3, true ><<<dim3((T2_ + 127) / 128, 8, B_), 256, G_SMEM>>>(pWk1, keys3, bk1, k1b, CTXT, 1024, 1536, T2_);
    gemm128_kernel<1, false><<<dim3((T2_ + 127) / 128, 1, B_), 256, G_SMEM>>>(pWk2, k1b, bk2, kfb, 1024, 80, 1024, T2_);

    // query path
    gemm128_kernel<3, true ><<<dim3((T1_ + 127) / 128, 2, B_), 256, G_SMEM>>>(pWq1, que3, bq1, q1b, CMEL, 160, 240, T1_);
    gemm128_kernel<1, true ><<<dim3((T1_ + 127) / 128, 1, B_), 256, G_SMEM>>>(pWq2, q1b, bq2, q2b, 160, 80, 160, T1_);
    gemm128_kernel<1, false><<<dim3((T1_ + 127) / 128, 1, B_), 256, G_SMEM>>>(pWq3, q2b, bq3, qfb, 80, 80, 80, T1_);

    // norms
    sumsq_bf16_kernel<<<dim3((T2_ + 255) / 256, B_), 256>>>(kfb, k2s, CATT, T2_);
    sumsq_bf16_kernel<<<dim3((T1_ + 255) / 256, B_), 256>>>(qfb, q2s, CATT, T1_);

    // fused attention epilogue (tensor-core qk)
    attn_mma_kernel<<<dim3(T1_ / 32, B_), 256, ATTN_SMEM>>>(qfb, kfb, q2s, k2s, prior, mask, attn_out, logp_out);
}